// round 2
// baseline (speedup 1.0000x reference)
#include <cuda_runtime.h>
#include <cuda_bf16.h>
#include <math.h>

// ---------------------------------------------------------------------------
// GatedDeltaNetVarlen: total=1536 tokens, HIDDEN=1024, HK=8, HV=16, DK=DV=64,
// KSZ=4, KEY_DIM=512, VAL_DIM=1024, CONV_DIM=2048.
// Pipeline:
//   1. mixed = h @ W_qkv^T ; z = h @ W_z^T ; b = h @ W_b^T ; a = h @ W_a^T
//   2. causal depthwise conv (per varlen sequence) + silu, split q/k/v,
//      per-head L2 norm of q,k ; beta = sigmoid(b) ; g = -exp(A_log)*softplus(a+dt_bias)
//   3. gated delta rule recurrence per (batch, value-head), 64x64 fp32 state
//   4. gated RMSNorm (gate = silu(z))
//   5. out = o @ W_out^T
// ---------------------------------------------------------------------------

#define TOTAL_MAX 1536
#define HIDDEN 1024
#define HK 8
#define HV 16
#define DK 64
#define DV 64
#define KEY_DIM 512
#define VAL_DIM 1024
#define CONV_DIM 2048

// scratch (static device globals; no allocation allowed)
__device__ float g_mixed[TOTAL_MAX * CONV_DIM];
__device__ float g_zbuf [TOTAL_MAX * VAL_DIM];
__device__ float g_bbuf [TOTAL_MAX * HV];
__device__ float g_abuf [TOTAL_MAX * HV];
__device__ float g_qn   [TOTAL_MAX * KEY_DIM];
__device__ float g_kn   [TOTAL_MAX * KEY_DIM];
__device__ float g_vv   [TOTAL_MAX * VAL_DIM];
__device__ float g_beta [TOTAL_MAX * HV];
__device__ float g_gate [TOTAL_MAX * HV];
__device__ float g_obuf [TOTAL_MAX * VAL_DIM];
__device__ float g_onrm [TOTAL_MAX * VAL_DIM];

// ---------------------------------------------------------------------------
// Generic C[M,N] = A[M,K] * B[N,K]^T   (both row-major; dot of rows)
// 64x64 tile, BK=16, 256 threads, 4x4 microtile per thread.
// ---------------------------------------------------------------------------
#define BM 64
#define BN 64
#define BKT 16

__global__ __launch_bounds__(256) void gemm_abt(
    const float* __restrict__ A, const float* __restrict__ B,
    float* __restrict__ C, int M, int N, int K)
{
    __shared__ float As[BKT][BM];
    __shared__ float Bs[BKT][BN];

    const int tid = threadIdx.x;
    const int tx = tid & 15;        // 0..15  (n dir)
    const int ty = tid >> 4;        // 0..15  (m dir)
    const int m0 = blockIdx.y * BM;
    const int n0 = blockIdx.x * BN;

    const int lrow = tid >> 2;          // 0..63
    const int lc4  = (tid & 3) << 2;    // 0,4,8,12

    float acc[4][4];
#pragma unroll
    for (int i = 0; i < 4; i++)
#pragma unroll
        for (int j = 0; j < 4; j++) acc[i][j] = 0.f;

    for (int k0 = 0; k0 < K; k0 += BKT) {
        float4 av = make_float4(0.f, 0.f, 0.f, 0.f);
        if (m0 + lrow < M)
            av = *(const float4*)(A + (size_t)(m0 + lrow) * K + k0 + lc4);
        As[lc4 + 0][lrow] = av.x;
        As[lc4 + 1][lrow] = av.y;
        As[lc4 + 2][lrow] = av.z;
        As[lc4 + 3][lrow] = av.w;

        float4 bv = make_float4(0.f, 0.f, 0.f, 0.f);
        if (n0 + lrow < N)
            bv = *(const float4*)(B + (size_t)(n0 + lrow) * K + k0 + lc4);
        Bs[lc4 + 0][lrow] = bv.x;
        Bs[lc4 + 1][lrow] = bv.y;
        Bs[lc4 + 2][lrow] = bv.z;
        Bs[lc4 + 3][lrow] = bv.w;

        __syncthreads();

#pragma unroll
        for (int kk = 0; kk < BKT; kk++) {
            float4 a = *(const float4*)&As[kk][ty << 2];
            float4 b = *(const float4*)&Bs[kk][tx << 2];
            acc[0][0] = fmaf(a.x, b.x, acc[0][0]);
            acc[0][1] = fmaf(a.x, b.y, acc[0][1]);
            acc[0][2] = fmaf(a.x, b.z, acc[0][2]);
            acc[0][3] = fmaf(a.x, b.w, acc[0][3]);
            acc[1][0] = fmaf(a.y, b.x, acc[1][0]);
            acc[1][1] = fmaf(a.y, b.y, acc[1][1]);
            acc[1][2] = fmaf(a.y, b.z, acc[1][2]);
            acc[1][3] = fmaf(a.y, b.w, acc[1][3]);
            acc[2][0] = fmaf(a.z, b.x, acc[2][0]);
            acc[2][1] = fmaf(a.z, b.y, acc[2][1]);
            acc[2][2] = fmaf(a.z, b.z, acc[2][2]);
            acc[2][3] = fmaf(a.z, b.w, acc[2][3]);
            acc[3][0] = fmaf(a.w, b.x, acc[3][0]);
            acc[3][1] = fmaf(a.w, b.y, acc[3][1]);
            acc[3][2] = fmaf(a.w, b.z, acc[3][2]);
            acc[3][3] = fmaf(a.w, b.w, acc[3][3]);
        }
        __syncthreads();
    }

#pragma unroll
    for (int i = 0; i < 4; i++) {
        int m = m0 + (ty << 2) + i;
        if (m >= M) continue;
#pragma unroll
        for (int j = 0; j < 4; j++) {
            int n = n0 + (tx << 2) + j;
            if (n < N) C[(size_t)m * N + n] = acc[i][j];
        }
    }
}

// ---------------------------------------------------------------------------
// Causal depthwise conv (KSZ=4) within each varlen sequence + silu,
// per-head L2 norm of q and k, v passthrough, plus beta/g gate computation.
// One block per token, 512 threads (each handles 4 channels c, c+512, ...).
// ---------------------------------------------------------------------------
__global__ __launch_bounds__(512) void conv_gate_kernel(
    const float* __restrict__ conv_w,
    const float* __restrict__ dt_bias, const float* __restrict__ A_log,
    const int* __restrict__ cu, int nseq)
{
    const int t = blockIdx.x;
    __shared__ float ybuf[CONV_DIM];
    __shared__ float ssq[16];

    int start = 0;
    for (int b = 0; b < nseq; b++) {
        int s = cu[b];
        if (t >= s) start = s;
    }

#pragma unroll
    for (int r = 0; r < 4; r++) {
        int c = threadIdx.x + 512 * r;
        float acc = 0.f;
#pragma unroll
        for (int j = 0; j < 4; j++) {
            int tt = t - 3 + j;
            if (tt >= start)
                acc = fmaf(conv_w[c * 4 + j], g_mixed[(size_t)tt * CONV_DIM + c], acc);
        }
        // silu
        ybuf[c] = acc / (1.f + expf(-acc));
    }
    __syncthreads();

    // per-head sum of squares for q (heads 0..7) and k (heads 8..15):
    // warp w reduces channels [w*64, w*64+64)
    {
        int w = threadIdx.x >> 5, lane = threadIdx.x & 31;
        float x0 = ybuf[w * 64 + lane];
        float x1 = ybuf[w * 64 + 32 + lane];
        float s2 = x0 * x0 + x1 * x1;
#pragma unroll
        for (int off = 16; off > 0; off >>= 1)
            s2 += __shfl_xor_sync(0xffffffffu, s2, off);
        if (lane == 0) ssq[w] = s2;
    }
    __syncthreads();

#pragma unroll
    for (int r = 0; r < 4; r++) {
        int c = threadIdx.x + 512 * r;
        float yv = ybuf[c];
        if (c < KEY_DIM) {
            int h = c >> 6;
            g_qn[(size_t)t * KEY_DIM + c] = yv * rsqrtf(ssq[h] + 1e-6f) * 0.125f; // DK^-0.5
        } else if (c < 2 * KEY_DIM) {
            int cc = c - KEY_DIM;
            int h = cc >> 6;
            g_kn[(size_t)t * KEY_DIM + cc] = yv * rsqrtf(ssq[8 + h] + 1e-6f);
        } else {
            g_vv[(size_t)t * VAL_DIM + (c - 2 * KEY_DIM)] = yv;
        }
    }

    if (threadIdx.x < HV) {
        int h = threadIdx.x;
        float bb = g_bbuf[t * HV + h];
        g_beta[t * HV + h] = 1.f / (1.f + expf(-bb));
        float aa = g_abuf[t * HV + h] + dt_bias[h];
        float sp = (aa > 20.f) ? aa : log1pf(expf(aa));
        g_gate[t * HV + h] = -expf(A_log[h]) * sp;
    }
}

// ---------------------------------------------------------------------------
// Gated delta rule recurrence. Grid (HV, nseq); 64 threads; thread j owns
// state column S[:, j] (64 registers).
// ---------------------------------------------------------------------------
__global__ __launch_bounds__(64) void delta_kernel(const int* __restrict__ cu)
{
    const int h = blockIdx.x;        // value head 0..15
    const int b = blockIdx.y;
    const int j = threadIdx.x;       // dv column 0..63
    const int start = cu[b], end = cu[b + 1];
    const int kh = h >> 1;           // GQA: q/k head = h / (HV/HK)

    float S[64];
#pragma unroll
    for (int i = 0; i < 64; i++) S[i] = 0.f;

    __shared__ float sk[64], sq[64];
    __shared__ float sg, sb;

    for (int t = start; t < end; t++) {
        sk[j] = g_kn[((size_t)t * HK + kh) * DK + j];
        sq[j] = g_qn[((size_t)t * HK + kh) * DK + j];
        if (j == 0) {
            sg = expf(g_gate[t * HV + h]);
            sb = g_beta[t * HV + h];
        }
        float vj = g_vv[((size_t)t * HV + h) * DV + j];
        __syncthreads();

        const float dec = sg, bt = sb;
        float kS0 = 0.f, kS1 = 0.f, kS2 = 0.f, kS3 = 0.f;
#pragma unroll
        for (int i = 0; i < 64; i += 4) {
            S[i + 0] *= dec; S[i + 1] *= dec; S[i + 2] *= dec; S[i + 3] *= dec;
            kS0 = fmaf(sk[i + 0], S[i + 0], kS0);
            kS1 = fmaf(sk[i + 1], S[i + 1], kS1);
            kS2 = fmaf(sk[i + 2], S[i + 2], kS2);
            kS3 = fmaf(sk[i + 3], S[i + 3], kS3);
        }
        const float delta = bt * (vj - ((kS0 + kS1) + (kS2 + kS3)));

        float o0 = 0.f, o1 = 0.f, o2 = 0.f, o3 = 0.f;
#pragma unroll
        for (int i = 0; i < 64; i += 4) {
            S[i + 0] = fmaf(sk[i + 0], delta, S[i + 0]);
            S[i + 1] = fmaf(sk[i + 1], delta, S[i + 1]);
            S[i + 2] = fmaf(sk[i + 2], delta, S[i + 2]);
            S[i + 3] = fmaf(sk[i + 3], delta, S[i + 3]);
            o0 = fmaf(sq[i + 0], S[i + 0], o0);
            o1 = fmaf(sq[i + 1], S[i + 1], o1);
            o2 = fmaf(sq[i + 2], S[i + 2], o2);
            o3 = fmaf(sq[i + 3], S[i + 3], o3);
        }
        g_obuf[((size_t)t * HV + h) * DV + j] = (o0 + o1) + (o2 + o3);
        __syncthreads();
    }
}

// ---------------------------------------------------------------------------
// Gated RMSNorm: o * rsqrt(mean(o^2)+eps) * norm_weight * silu(z)
// One block per token, 256 threads (16 lanes x 4 elems per head).
// ---------------------------------------------------------------------------
__global__ __launch_bounds__(256) void gated_norm_kernel(const float* __restrict__ nw)
{
    const int t = blockIdx.x;
    const int tid = threadIdx.x;
    const int h = tid >> 4;         // 0..15
    const int s = tid & 15;         // 0..15

    const size_t base = ((size_t)t * HV + h) * DV + s * 4;
    float4 o4 = *(const float4*)(g_obuf + base);
    float ss = o4.x * o4.x + o4.y * o4.y + o4.z * o4.z + o4.w * o4.w;
    ss += __shfl_xor_sync(0xffffffffu, ss, 8);
    ss += __shfl_xor_sync(0xffffffffu, ss, 4);
    ss += __shfl_xor_sync(0xffffffffu, ss, 2);
    ss += __shfl_xor_sync(0xffffffffu, ss, 1);
    const float r = rsqrtf(ss * (1.f / 64.f) + 1e-6f);

    float4 z4 = *(const float4*)(g_zbuf + (size_t)t * VAL_DIM + h * DV + s * 4);
    float4 w4 = *(const float4*)(nw + s * 4);
    float4 out;
    out.x = o4.x * r * w4.x * (z4.x / (1.f + expf(-z4.x)));
    out.y = o4.y * r * w4.y * (z4.y / (1.f + expf(-z4.y)));
    out.z = o4.z * r * w4.z * (z4.z / (1.f + expf(-z4.z)));
    out.w = o4.w * r * w4.w * (z4.w / (1.f + expf(-z4.w)));
    *(float4*)(g_onrm + (size_t)t * VAL_DIM + h * DV + s * 4) = out;
}

// ---------------------------------------------------------------------------
extern "C" void kernel_launch(void* const* d_in, const int* in_sizes, int n_in,
                              void* d_out, int out_size)
{
    const float* hidden  = (const float*)d_in[0];
    const float* W_qkv   = (const float*)d_in[1];
    const float* W_z     = (const float*)d_in[2];
    const float* W_b     = (const float*)d_in[3];
    const float* W_a     = (const float*)d_in[4];
    const float* conv_w  = (const float*)d_in[5];
    const float* dt_bias = (const float*)d_in[6];
    const float* A_log   = (const float*)d_in[7];
    const float* nw      = (const float*)d_in[8];
    const float* W_out   = (const float*)d_in[9];
    const int*   cu      = (const int*)d_in[10];

    const int total = in_sizes[0] / HIDDEN;
    const int nseq  = in_sizes[10] - 1;

    float *mixed, *zb, *bb, *ab, *on;
    cudaGetSymbolAddress((void**)&mixed, g_mixed);
    cudaGetSymbolAddress((void**)&zb,    g_zbuf);
    cudaGetSymbolAddress((void**)&bb,    g_bbuf);
    cudaGetSymbolAddress((void**)&ab,    g_abuf);
    cudaGetSymbolAddress((void**)&on,    g_onrm);

    const int mBlocks = (total + BM - 1) / BM;

    // 1. projections
    gemm_abt<<<dim3(CONV_DIM / BN, mBlocks), 256>>>(hidden, W_qkv, mixed, total, CONV_DIM, HIDDEN);
    gemm_abt<<<dim3(VAL_DIM / BN,  mBlocks), 256>>>(hidden, W_z,   zb,    total, VAL_DIM,  HIDDEN);
    gemm_abt<<<dim3(1,             mBlocks), 256>>>(hidden, W_b,   bb,    total, HV,       HIDDEN);
    gemm_abt<<<dim3(1,             mBlocks), 256>>>(hidden, W_a,   ab,    total, HV,       HIDDEN);

    // 2. conv + silu + norms + gates
    conv_gate_kernel<<<total, 512>>>(conv_w, dt_bias, A_log, cu, nseq);

    // 3. recurrence
    delta_kernel<<<dim3(HV, nseq), 64>>>(cu);

    // 4. gated RMSNorm
    gated_norm_kernel<<<total, 256>>>(nw);

    // 5. output projection
    gemm_abt<<<dim3(VAL_DIM / BN, mBlocks), 256>>>(on, W_out, (float*)d_out, total, HIDDEN, HIDDEN);
}

// round 3
// speedup vs baseline: 1.3930x; 1.3930x over previous
#include <cuda_runtime.h>
#include <cuda_bf16.h>
#include <math.h>

// ---------------------------------------------------------------------------
// GatedDeltaNetVarlen  (total=1536, HIDDEN=1024, HK=8, HV=16, DK=DV=64, KSZ=4)
// R3: tf32 mma.sync GEMMs + fused small projections + f32x2 recurrence.
// ---------------------------------------------------------------------------

#define TOTAL_MAX 1536
#define HIDDEN 1024
#define HK 8
#define HV 16
#define DK 64
#define DV 64
#define KEY_DIM 512
#define VAL_DIM 1024
#define CONV_DIM 2048

__device__ __align__(16) float g_mixed[TOTAL_MAX * CONV_DIM];
__device__ __align__(16) float g_zbuf [TOTAL_MAX * VAL_DIM];
__device__ __align__(16) float g_bbuf [TOTAL_MAX * HV];
__device__ __align__(16) float g_abuf [TOTAL_MAX * HV];
__device__ __align__(16) float g_qn   [TOTAL_MAX * KEY_DIM];
__device__ __align__(16) float g_kn   [TOTAL_MAX * KEY_DIM];
__device__ __align__(16) float g_vv   [TOTAL_MAX * VAL_DIM];
__device__ __align__(16) float g_beta [TOTAL_MAX * HV];
__device__ __align__(16) float g_gate [TOTAL_MAX * HV];
__device__ __align__(16) float g_obuf [TOTAL_MAX * VAL_DIM];
__device__ __align__(16) float g_onrm [TOTAL_MAX * VAL_DIM];

// ------------------------------ helpers ------------------------------------
__device__ __forceinline__ unsigned f2tf32(float x) {
    unsigned u;
    asm("cvt.rna.tf32.f32 %0, %1;" : "=r"(u) : "f"(x));
    return u;
}

__device__ __forceinline__ unsigned long long pk2(float a, float b) {
    unsigned long long r;
    asm("mov.b64 %0, {%1,%2};" : "=l"(r) : "f"(a), "f"(b));
    return r;
}
__device__ __forceinline__ void upk2(unsigned long long v, float& a, float& b) {
    asm("mov.b64 {%0,%1}, %2;" : "=f"(a), "=f"(b) : "l"(v));
}
__device__ __forceinline__ unsigned long long fma2(
    unsigned long long a, unsigned long long b, unsigned long long c) {
    unsigned long long d;
    asm("fma.rn.f32x2 %0, %1, %2, %3;" : "=l"(d) : "l"(a), "l"(b), "l"(c));
    return d;
}
__device__ __forceinline__ unsigned long long mul2(
    unsigned long long a, unsigned long long b) {
    unsigned long long d;
    asm("mul.rn.f32x2 %0, %1, %2;" : "=l"(d) : "l"(a), "l"(b));
    return d;
}

// ---------------------------------------------------------------------------
// tf32 tensor-core GEMM:  C[M,N] = A[M,K] * B[N,K]^T
// Block 128 threads (4 warps 2x2), BM=128, BN=64, BK=32, warp tile 64x32.
// mma.sync.aligned.m16n8k8.row.col.f32.tf32.tf32.f32
// ---------------------------------------------------------------------------
#define PA 136   // smem pitch for A[k][m]  (8k mod 32 spread -> conflict-free)
#define PB 72    // smem pitch for B[k][n]

__global__ __launch_bounds__(128) void gemm_tf32(
    const float* __restrict__ A, const float* __restrict__ B,
    float* __restrict__ C, int M, int N, int K)
{
    __shared__ unsigned As[32 * PA];
    __shared__ unsigned Bs[32 * PB];

    const int tid  = threadIdx.x;
    const int lane = tid & 31;
    const int wid  = tid >> 5;
    const int wm   = wid >> 1;            // 0,1
    const int wn   = wid & 1;             // 0,1
    const int gid  = lane >> 2;           // 0..7
    const int tig  = lane & 3;            // 0..3

    const int m0 = blockIdx.y * 128;
    const int n0 = blockIdx.x * 64;

    const int am = m0 + tid;              // staging row for A
    const bool aok = am < M;
    const int bn = tid & 63;              // staging row for B
    const int bkh = tid >> 6;             // 0,1 (k half)
    const bool bok = (n0 + bn) < N;

    float acc[4][4][4];
#pragma unroll
    for (int i = 0; i < 4; i++)
#pragma unroll
        for (int j = 0; j < 4; j++)
#pragma unroll
            for (int v = 0; v < 4; v++) acc[i][j][v] = 0.f;

    const int iters = K / 32;
    float4 Ar[8], Br[4];

    // prefetch iter 0
    {
        const float4* Ag = (const float4*)(A + (size_t)am * K);
        const float4* Bg = (const float4*)(B + (size_t)(n0 + bn) * K + bkh * 16);
#pragma unroll
        for (int g = 0; g < 8; g++)
            Ar[g] = aok ? Ag[g] : make_float4(0.f, 0.f, 0.f, 0.f);
#pragma unroll
        for (int g = 0; g < 4; g++)
            Br[g] = bok ? Bg[g] : make_float4(0.f, 0.f, 0.f, 0.f);
    }

    for (int it = 0; it < iters; it++) {
        __syncthreads();
#pragma unroll
        for (int g = 0; g < 8; g++) {
            As[(4 * g + 0) * PA + tid] = f2tf32(Ar[g].x);
            As[(4 * g + 1) * PA + tid] = f2tf32(Ar[g].y);
            As[(4 * g + 2) * PA + tid] = f2tf32(Ar[g].z);
            As[(4 * g + 3) * PA + tid] = f2tf32(Ar[g].w);
        }
#pragma unroll
        for (int g = 0; g < 4; g++) {
            int kk = bkh * 16 + 4 * g;
            Bs[(kk + 0) * PB + bn] = f2tf32(Br[g].x);
            Bs[(kk + 1) * PB + bn] = f2tf32(Br[g].y);
            Bs[(kk + 2) * PB + bn] = f2tf32(Br[g].z);
            Bs[(kk + 3) * PB + bn] = f2tf32(Br[g].w);
        }
        __syncthreads();

        if (it + 1 < iters) {
            int k0 = (it + 1) * 32;
            const float4* Ag = (const float4*)(A + (size_t)am * K + k0);
            const float4* Bg = (const float4*)(B + (size_t)(n0 + bn) * K + k0 + bkh * 16);
#pragma unroll
            for (int g = 0; g < 8; g++)
                Ar[g] = aok ? Ag[g] : make_float4(0.f, 0.f, 0.f, 0.f);
#pragma unroll
            for (int g = 0; g < 4; g++)
                Br[g] = bok ? Bg[g] : make_float4(0.f, 0.f, 0.f, 0.f);
        }

#pragma unroll
        for (int s = 0; s < 4; s++) {
            unsigned af[4][4], bf[4][2];
#pragma unroll
            for (int mt = 0; mt < 4; mt++) {
                int mA = wm * 64 + mt * 16 + gid;
                int kr = s * 8 + tig;
                af[mt][0] = As[kr * PA + mA];
                af[mt][1] = As[kr * PA + mA + 8];
                af[mt][2] = As[(kr + 4) * PA + mA];
                af[mt][3] = As[(kr + 4) * PA + mA + 8];
            }
#pragma unroll
            for (int nt = 0; nt < 4; nt++) {
                int nB = wn * 32 + nt * 8 + gid;
                int kr = s * 8 + tig;
                bf[nt][0] = Bs[kr * PB + nB];
                bf[nt][1] = Bs[(kr + 4) * PB + nB];
            }
#pragma unroll
            for (int mt = 0; mt < 4; mt++)
#pragma unroll
                for (int nt = 0; nt < 4; nt++) {
                    asm volatile(
                        "mma.sync.aligned.m16n8k8.row.col.f32.tf32.tf32.f32 "
                        "{%0,%1,%2,%3}, {%4,%5,%6,%7}, {%8,%9}, {%0,%1,%2,%3};"
                        : "+f"(acc[mt][nt][0]), "+f"(acc[mt][nt][1]),
                          "+f"(acc[mt][nt][2]), "+f"(acc[mt][nt][3])
                        : "r"(af[mt][0]), "r"(af[mt][1]), "r"(af[mt][2]), "r"(af[mt][3]),
                          "r"(bf[nt][0]), "r"(bf[nt][1]));
                }
        }
    }

    // epilogue
#pragma unroll
    for (int mt = 0; mt < 4; mt++) {
        int row = m0 + wm * 64 + mt * 16 + gid;
#pragma unroll
        for (int nt = 0; nt < 4; nt++) {
            int col = n0 + wn * 32 + nt * 8 + tig * 2;
            if (row < M) {
                *(float2*)(C + (size_t)row * N + col) =
                    make_float2(acc[mt][nt][0], acc[mt][nt][1]);
            }
            if (row + 8 < M) {
                *(float2*)(C + (size_t)(row + 8) * N + col) =
                    make_float2(acc[mt][nt][2], acc[mt][nt][3]);
            }
        }
    }
}

// ---------------------------------------------------------------------------
// Fused small projections: b = h@W_b^T, a = h@W_a^T  (N=16 each).
// One block per token, 128 threads: 32 outputs x 4 partial lanes.
// ---------------------------------------------------------------------------
__global__ __launch_bounds__(128) void small_proj_kernel(
    const float* __restrict__ hs,
    const float* __restrict__ W_b, const float* __restrict__ W_a)
{
    const int t = blockIdx.x;
    __shared__ float sh[HIDDEN];

    // load hidden row
    {
        const float4* hp = (const float4*)(hs + (size_t)t * HIDDEN);
        float4* sp = (float4*)sh;
        sp[threadIdx.x]       = hp[threadIdx.x];
        sp[threadIdx.x + 128] = hp[threadIdx.x + 128];
    }
    __syncthreads();

    const int out  = threadIdx.x >> 2;   // 0..31
    const int part = threadIdx.x & 3;    // 0..3
    const float* W = (out < 16) ? (W_b + (size_t)out * HIDDEN)
                                : (W_a + (size_t)(out - 16) * HIDDEN);
    const float4* W4 = (const float4*)(W + part * 256);
    const float4* S4 = (const float4*)(sh + part * 256);

    float a0 = 0.f, a1 = 0.f;
#pragma unroll 8
    for (int i = 0; i < 64; i += 2) {
        float4 w = W4[i],     s = S4[i];
        float4 w2 = W4[i + 1], s2 = S4[i + 1];
        a0 = fmaf(w.x, s.x, a0);  a0 = fmaf(w.y, s.y, a0);
        a0 = fmaf(w.z, s.z, a0);  a0 = fmaf(w.w, s.w, a0);
        a1 = fmaf(w2.x, s2.x, a1); a1 = fmaf(w2.y, s2.y, a1);
        a1 = fmaf(w2.z, s2.z, a1); a1 = fmaf(w2.w, s2.w, a1);
    }
    float acc = a0 + a1;
    acc += __shfl_xor_sync(0xffffffffu, acc, 1);
    acc += __shfl_xor_sync(0xffffffffu, acc, 2);
    if (part == 0) {
        if (out < 16) g_bbuf[t * HV + out] = acc;
        else          g_abuf[t * HV + (out - 16)] = acc;
    }
}

// ---------------------------------------------------------------------------
// Causal depthwise conv (KSZ=4) + silu + per-head L2 norm + gates.
// ---------------------------------------------------------------------------
__global__ __launch_bounds__(512) void conv_gate_kernel(
    const float* __restrict__ conv_w,
    const float* __restrict__ dt_bias, const float* __restrict__ A_log,
    const int* __restrict__ cu, int nseq)
{
    const int t = blockIdx.x;
    __shared__ float ybuf[CONV_DIM];
    __shared__ float ssq[16];

    int start = 0;
    for (int b = 0; b < nseq; b++) {
        int s = cu[b];
        if (t >= s) start = s;
    }

#pragma unroll
    for (int r = 0; r < 4; r++) {
        int c = threadIdx.x + 512 * r;
        float acc = 0.f;
#pragma unroll
        for (int j = 0; j < 4; j++) {
            int tt = t - 3 + j;
            if (tt >= start)
                acc = fmaf(conv_w[c * 4 + j], g_mixed[(size_t)tt * CONV_DIM + c], acc);
        }
        ybuf[c] = acc / (1.f + expf(-acc));
    }
    __syncthreads();

    {
        int w = threadIdx.x >> 5, lane = threadIdx.x & 31;
        float x0 = ybuf[w * 64 + lane];
        float x1 = ybuf[w * 64 + 32 + lane];
        float s2 = x0 * x0 + x1 * x1;
#pragma unroll
        for (int off = 16; off > 0; off >>= 1)
            s2 += __shfl_xor_sync(0xffffffffu, s2, off);
        if (lane == 0) ssq[w] = s2;
    }
    __syncthreads();

#pragma unroll
    for (int r = 0; r < 4; r++) {
        int c = threadIdx.x + 512 * r;
        float yv = ybuf[c];
        if (c < KEY_DIM) {
            int h = c >> 6;
            g_qn[(size_t)t * KEY_DIM + c] = yv * rsqrtf(ssq[h] + 1e-6f) * 0.125f;
        } else if (c < 2 * KEY_DIM) {
            int cc = c - KEY_DIM;
            int h = cc >> 6;
            g_kn[(size_t)t * KEY_DIM + cc] = yv * rsqrtf(ssq[8 + h] + 1e-6f);
        } else {
            g_vv[(size_t)t * VAL_DIM + (c - 2 * KEY_DIM)] = yv;
        }
    }

    if (threadIdx.x < HV) {
        int h = threadIdx.x;
        float bb = g_bbuf[t * HV + h];
        g_beta[t * HV + h] = 1.f / (1.f + expf(-bb));
        float aa = g_abuf[t * HV + h] + dt_bias[h];
        float sp = (aa > 20.f) ? aa : log1pf(expf(aa));
        g_gate[t * HV + h] = -expf(A_log[h]) * sp;
    }
}

// ---------------------------------------------------------------------------
// Gated delta rule recurrence, f32x2 packed math.
// grid (HV, nseq, 2): blockIdx.z splits 64 dv-columns into 2x32.
// 128 threads: column c = tid>>2 (0..31), row-group r = tid&3 (16 rows each).
// All reductions intra-warp (4 lanes per column) via shfl; no __syncthreads.
// ---------------------------------------------------------------------------
__global__ __launch_bounds__(128) void delta_kernel(const int* __restrict__ cu)
{
    const int h  = blockIdx.x;
    const int b  = blockIdx.y;
    const int j  = blockIdx.z * 32 + (threadIdx.x >> 2);  // dv column
    const int r  = threadIdx.x & 3;                        // row group
    const int i0 = r * 16;
    const int kh = h >> 1;
    const int start = cu[b], end = cu[b + 1];

    unsigned long long S2[8];
#pragma unroll
    for (int i = 0; i < 8; i++) S2[i] = 0ULL;

    unsigned long long K2[8], Q2[8], Kn[8], Qn[8];
    float vc, gc, bc, vn, gn, bn;

    auto loadT = [&](int t, unsigned long long* kk, unsigned long long* qq,
                     float& v_, float& g_, float& b_) {
        const ulonglong2* kp = (const ulonglong2*)(g_kn + (size_t)t * KEY_DIM + kh * DK + i0);
        const ulonglong2* qp = (const ulonglong2*)(g_qn + (size_t)t * KEY_DIM + kh * DK + i0);
#pragma unroll
        for (int m = 0; m < 4; m++) {
            ulonglong2 ku = kp[m], qu = qp[m];
            kk[2 * m] = ku.x; kk[2 * m + 1] = ku.y;
            qq[2 * m] = qu.x; qq[2 * m + 1] = qu.y;
        }
        v_ = g_vv[(size_t)t * VAL_DIM + h * DV + j];
        g_ = g_gate[t * HV + h];
        b_ = g_beta[t * HV + h];
    };

    if (start < end) loadT(start, K2, Q2, vc, gc, bc);

    for (int t = start; t < end; t++) {
        // prefetch next step
        int tn = (t + 1 < end) ? (t + 1) : t;
        loadT(tn, Kn, Qn, vn, gn, bn);

        const float dec = expf(gc);

        // kS = k . S_old   (partial over 16 rows, 2 chains)
        unsigned long long p0 = 0ULL, p1 = 0ULL;
#pragma unroll
        for (int m = 0; m < 8; m += 2) {
            p0 = fma2(K2[m],     S2[m],     p0);
            p1 = fma2(K2[m + 1], S2[m + 1], p1);
        }
        float lo0, hi0, lo1, hi1;
        upk2(p0, lo0, hi0); upk2(p1, lo1, hi1);
        float ks = (lo0 + hi0) + (lo1 + hi1);
        ks += __shfl_xor_sync(0xffffffffu, ks, 1);
        ks += __shfl_xor_sync(0xffffffffu, ks, 2);

        const float delta = bc * (vc - dec * ks);
        const unsigned long long d2 = pk2(delta, delta);
        const unsigned long long dc2 = pk2(dec, dec);

        // S = dec*S + k*delta ;  o = q . S_new
        unsigned long long o0 = 0ULL, o1 = 0ULL;
#pragma unroll
        for (int m = 0; m < 8; m += 2) {
            unsigned long long kd0 = mul2(K2[m], d2);
            unsigned long long kd1 = mul2(K2[m + 1], d2);
            S2[m]     = fma2(dc2, S2[m],     kd0);
            S2[m + 1] = fma2(dc2, S2[m + 1], kd1);
            o0 = fma2(Q2[m],     S2[m],     o0);
            o1 = fma2(Q2[m + 1], S2[m + 1], o1);
        }
        upk2(o0, lo0, hi0); upk2(o1, lo1, hi1);
        float oo = (lo0 + hi0) + (lo1 + hi1);
        oo += __shfl_xor_sync(0xffffffffu, oo, 1);
        oo += __shfl_xor_sync(0xffffffffu, oo, 2);
        if (r == 0) g_obuf[(size_t)t * VAL_DIM + h * DV + j] = oo;

        // rotate prefetch
#pragma unroll
        for (int m = 0; m < 8; m++) { K2[m] = Kn[m]; Q2[m] = Qn[m]; }
        vc = vn; gc = gn; bc = bn;
    }
}

// ---------------------------------------------------------------------------
// Gated RMSNorm: o * rsqrt(mean(o^2)+eps) * norm_weight * silu(z)
// ---------------------------------------------------------------------------
__global__ __launch_bounds__(256) void gated_norm_kernel(const float* __restrict__ nw)
{
    const int t = blockIdx.x;
    const int tid = threadIdx.x;
    const int h = tid >> 4;
    const int s = tid & 15;

    const size_t base = ((size_t)t * HV + h) * DV + s * 4;
    float4 o4 = *(const float4*)(g_obuf + base);
    float ss = o4.x * o4.x + o4.y * o4.y + o4.z * o4.z + o4.w * o4.w;
    ss += __shfl_xor_sync(0xffffffffu, ss, 8);
    ss += __shfl_xor_sync(0xffffffffu, ss, 4);
    ss += __shfl_xor_sync(0xffffffffu, ss, 2);
    ss += __shfl_xor_sync(0xffffffffu, ss, 1);
    const float rr = rsqrtf(ss * (1.f / 64.f) + 1e-6f);

    float4 z4 = *(const float4*)(g_zbuf + (size_t)t * VAL_DIM + h * DV + s * 4);
    float4 w4 = *(const float4*)(nw + s * 4);
    float4 out;
    out.x = o4.x * rr * w4.x * (z4.x / (1.f + expf(-z4.x)));
    out.y = o4.y * rr * w4.y * (z4.y / (1.f + expf(-z4.y)));
    out.z = o4.z * rr * w4.z * (z4.z / (1.f + expf(-z4.z)));
    out.w = o4.w * rr * w4.w * (z4.w / (1.f + expf(-z4.w)));
    *(float4*)(g_onrm + base) = out;
}

// ---------------------------------------------------------------------------
extern "C" void kernel_launch(void* const* d_in, const int* in_sizes, int n_in,
                              void* d_out, int out_size)
{
    const float* hidden  = (const float*)d_in[0];
    const float* W_qkv   = (const float*)d_in[1];
    const float* W_z     = (const float*)d_in[2];
    const float* W_b     = (const float*)d_in[3];
    const float* W_a     = (const float*)d_in[4];
    const float* conv_w  = (const float*)d_in[5];
    const float* dt_bias = (const float*)d_in[6];
    const float* A_log   = (const float*)d_in[7];
    const float* nw      = (const float*)d_in[8];
    const float* W_out   = (const float*)d_in[9];
    const int*   cu      = (const int*)d_in[10];

    const int total = in_sizes[0] / HIDDEN;
    const int nseq  = in_sizes[10] - 1;

    float *mixed, *zb, *on;
    cudaGetSymbolAddress((void**)&mixed, g_mixed);
    cudaGetSymbolAddress((void**)&zb,    g_zbuf);
    cudaGetSymbolAddress((void**)&on,    g_onrm);

    const int mB = (total + 127) / 128;

    // 1. big projections (tf32 tensor cores)
    gemm_tf32<<<dim3(CONV_DIM / 64, mB), 128>>>(hidden, W_qkv, mixed, total, CONV_DIM, HIDDEN);
    gemm_tf32<<<dim3(VAL_DIM / 64,  mB), 128>>>(hidden, W_z,   zb,    total, VAL_DIM,  HIDDEN);

    // 2. small projections (b, a fused)
    small_proj_kernel<<<total, 128>>>(hidden, W_b, W_a);

    // 3. conv + silu + norms + gates
    conv_gate_kernel<<<total, 512>>>(conv_w, dt_bias, A_log, cu, nseq);

    // 4. recurrence
    delta_kernel<<<dim3(HV, nseq, 2), 128>>>(cu);

    // 5. gated RMSNorm
    gated_norm_kernel<<<total, 256>>>(nw);

    // 6. output projection
    gemm_tf32<<<dim3(VAL_DIM / 64, mB), 128>>>(on, W_out, (float*)d_out, total, HIDDEN, HIDDEN);
}

// round 4
// speedup vs baseline: 1.8200x; 1.3065x over previous
#include <cuda_runtime.h>
#include <cuda_bf16.h>
#include <math.h>

// ---------------------------------------------------------------------------
// GatedDeltaNetVarlen  (total=1536, HIDDEN=1024, HK=8, HV=16, DK=DV=64, KSZ=4)
// R4: coalesced-staging tf32 mma GEMM (fix L1-wavefront-bound staging of R3).
// ---------------------------------------------------------------------------

#define TOTAL_MAX 1536
#define HIDDEN 1024
#define HK 8
#define HV 16
#define DK 64
#define DV 64
#define KEY_DIM 512
#define VAL_DIM 1024
#define CONV_DIM 2048

__device__ __align__(16) float g_mixed[TOTAL_MAX * CONV_DIM];
__device__ __align__(16) float g_zbuf [TOTAL_MAX * VAL_DIM];
__device__ __align__(16) float g_bbuf [TOTAL_MAX * HV];
__device__ __align__(16) float g_abuf [TOTAL_MAX * HV];
__device__ __align__(16) float g_qn   [TOTAL_MAX * KEY_DIM];
__device__ __align__(16) float g_kn   [TOTAL_MAX * KEY_DIM];
__device__ __align__(16) float g_vv   [TOTAL_MAX * VAL_DIM];
__device__ __align__(16) float g_beta [TOTAL_MAX * HV];
__device__ __align__(16) float g_gate [TOTAL_MAX * HV];
__device__ __align__(16) float g_obuf [TOTAL_MAX * VAL_DIM];
__device__ __align__(16) float g_onrm [TOTAL_MAX * VAL_DIM];

// ------------------------------ helpers ------------------------------------
__device__ __forceinline__ unsigned f2tf32(float x) {
    unsigned u;
    asm("cvt.rna.tf32.f32 %0, %1;" : "=r"(u) : "f"(x));
    return u;
}
__device__ __forceinline__ unsigned long long pk2(float a, float b) {
    unsigned long long r;
    asm("mov.b64 %0, {%1,%2};" : "=l"(r) : "f"(a), "f"(b));
    return r;
}
__device__ __forceinline__ void upk2(unsigned long long v, float& a, float& b) {
    asm("mov.b64 {%0,%1}, %2;" : "=f"(a), "=f"(b) : "l"(v));
}
__device__ __forceinline__ unsigned long long fma2(
    unsigned long long a, unsigned long long b, unsigned long long c) {
    unsigned long long d;
    asm("fma.rn.f32x2 %0, %1, %2, %3;" : "=l"(d) : "l"(a), "l"(b), "l"(c));
    return d;
}
__device__ __forceinline__ unsigned long long mul2(
    unsigned long long a, unsigned long long b) {
    unsigned long long d;
    asm("mul.rn.f32x2 %0, %1, %2;" : "=l"(d) : "l"(a), "l"(b));
    return d;
}

// ---------------------------------------------------------------------------
// tf32 tensor-core GEMM:  C[M,N] = A[M,K] * B[N,K]^T
// 256 threads (8 warps as 4m x 2n), BM=128, BN=64, BK=32, warp tile 32x32.
// Coalesced staging: 8 threads/row, each warp LDG.128 touches 4 lines.
// Smem row-major [m][k], pitch 36 words: fragment reads conflict-free
// (bank = 4*gid + tig, unique over the warp).
// ---------------------------------------------------------------------------
#define PAD 36

__global__ __launch_bounds__(256) void gemm_tf32(
    const float* __restrict__ A, const float* __restrict__ B,
    float* __restrict__ C, int M, int N, int K)
{
    __shared__ unsigned As[128 * PAD];
    __shared__ unsigned Bs[64 * PAD];

    const int tid  = threadIdx.x;
    const int lane = tid & 31;
    const int wid  = tid >> 5;
    const int wm   = wid >> 1;        // 0..3
    const int wn   = wid & 1;         // 0..1
    const int gid  = lane >> 2;       // 0..7
    const int tig  = lane & 3;        // 0..3

    const int m0 = blockIdx.y * 128;
    const int n0 = blockIdx.x * 64;

    const int srow = tid >> 3;            // 0..31
    const int scol = (tid & 7) << 2;      // 0,4,...,28

    float acc[2][4][4];
#pragma unroll
    for (int i = 0; i < 2; i++)
#pragma unroll
        for (int j = 0; j < 4; j++)
#pragma unroll
            for (int v = 0; v < 4; v++) acc[i][j][v] = 0.f;

    const int iters = K / 32;
    float4 Ar[4], Br[2];

    // prefetch iter 0 (coalesced: 8 threads per row)
#pragma unroll
    for (int p = 0; p < 4; p++) {
        int r = srow + 32 * p;
        Ar[p] = (m0 + r < M) ? *(const float4*)(A + (size_t)(m0 + r) * K + scol)
                             : make_float4(0.f, 0.f, 0.f, 0.f);
    }
#pragma unroll
    for (int p = 0; p < 2; p++) {
        int r = srow + 32 * p;
        Br[p] = (n0 + r < N) ? *(const float4*)(B + (size_t)(n0 + r) * K + scol)
                             : make_float4(0.f, 0.f, 0.f, 0.f);
    }

    for (int it = 0; it < iters; it++) {
        if (it > 0) __syncthreads();   // WAR: previous compute done before overwrite

#pragma unroll
        for (int p = 0; p < 4; p++) {
            int r = srow + 32 * p;
            uint4 u = make_uint4(f2tf32(Ar[p].x), f2tf32(Ar[p].y),
                                 f2tf32(Ar[p].z), f2tf32(Ar[p].w));
            *(uint4*)&As[r * PAD + scol] = u;
        }
#pragma unroll
        for (int p = 0; p < 2; p++) {
            int r = srow + 32 * p;
            uint4 u = make_uint4(f2tf32(Br[p].x), f2tf32(Br[p].y),
                                 f2tf32(Br[p].z), f2tf32(Br[p].w));
            *(uint4*)&Bs[r * PAD + scol] = u;
        }
        __syncthreads();

        if (it + 1 < iters) {
            int k0 = (it + 1) * 32;
#pragma unroll
            for (int p = 0; p < 4; p++) {
                int r = srow + 32 * p;
                Ar[p] = (m0 + r < M)
                      ? *(const float4*)(A + (size_t)(m0 + r) * K + k0 + scol)
                      : make_float4(0.f, 0.f, 0.f, 0.f);
            }
#pragma unroll
            for (int p = 0; p < 2; p++) {
                int r = srow + 32 * p;
                Br[p] = (n0 + r < N)
                      ? *(const float4*)(B + (size_t)(n0 + r) * K + k0 + scol)
                      : make_float4(0.f, 0.f, 0.f, 0.f);
            }
        }

#pragma unroll
        for (int s = 0; s < 4; s++) {
            const int ks = s * 8;
            unsigned af[2][4], bf[4][2];
#pragma unroll
            for (int mt = 0; mt < 2; mt++) {
                int mr = wm * 32 + mt * 16 + gid;
                af[mt][0] = As[mr * PAD + ks + tig];
                af[mt][1] = As[(mr + 8) * PAD + ks + tig];
                af[mt][2] = As[mr * PAD + ks + tig + 4];
                af[mt][3] = As[(mr + 8) * PAD + ks + tig + 4];
            }
#pragma unroll
            for (int nt = 0; nt < 4; nt++) {
                int nr = wn * 32 + nt * 8 + gid;
                bf[nt][0] = Bs[nr * PAD + ks + tig];
                bf[nt][1] = Bs[nr * PAD + ks + tig + 4];
            }
#pragma unroll
            for (int mt = 0; mt < 2; mt++)
#pragma unroll
                for (int nt = 0; nt < 4; nt++) {
                    asm volatile(
                        "mma.sync.aligned.m16n8k8.row.col.f32.tf32.tf32.f32 "
                        "{%0,%1,%2,%3}, {%4,%5,%6,%7}, {%8,%9}, {%0,%1,%2,%3};"
                        : "+f"(acc[mt][nt][0]), "+f"(acc[mt][nt][1]),
                          "+f"(acc[mt][nt][2]), "+f"(acc[mt][nt][3])
                        : "r"(af[mt][0]), "r"(af[mt][1]), "r"(af[mt][2]), "r"(af[mt][3]),
                          "r"(bf[nt][0]), "r"(bf[nt][1]));
                }
        }
    }

    // epilogue: c0,c1 -> (gid, tig*2(+1)); c2,c3 -> (gid+8, ...)
#pragma unroll
    for (int mt = 0; mt < 2; mt++) {
        int row = m0 + wm * 32 + mt * 16 + gid;
#pragma unroll
        for (int nt = 0; nt < 4; nt++) {
            int col = n0 + wn * 32 + nt * 8 + tig * 2;
            if (row < M)
                *(float2*)(C + (size_t)row * N + col) =
                    make_float2(acc[mt][nt][0], acc[mt][nt][1]);
            if (row + 8 < M)
                *(float2*)(C + (size_t)(row + 8) * N + col) =
                    make_float2(acc[mt][nt][2], acc[mt][nt][3]);
        }
    }
}

// ---------------------------------------------------------------------------
// Fused small projections: b = h@W_b^T, a = h@W_a^T  (N=16 each).
// ---------------------------------------------------------------------------
__global__ __launch_bounds__(128) void small_proj_kernel(
    const float* __restrict__ hs,
    const float* __restrict__ W_b, const float* __restrict__ W_a)
{
    const int t = blockIdx.x;
    __shared__ float sh[HIDDEN];

    {
        const float4* hp = (const float4*)(hs + (size_t)t * HIDDEN);
        float4* sp = (float4*)sh;
        sp[threadIdx.x]       = hp[threadIdx.x];
        sp[threadIdx.x + 128] = hp[threadIdx.x + 128];
    }
    __syncthreads();

    const int out  = threadIdx.x >> 2;
    const int part = threadIdx.x & 3;
    const float* W = (out < 16) ? (W_b + (size_t)out * HIDDEN)
                                : (W_a + (size_t)(out - 16) * HIDDEN);
    const float4* W4 = (const float4*)(W + part * 256);
    const float4* S4 = (const float4*)(sh + part * 256);

    float a0 = 0.f, a1 = 0.f;
#pragma unroll 8
    for (int i = 0; i < 64; i += 2) {
        float4 w = W4[i],      s = S4[i];
        float4 w2 = W4[i + 1], s2 = S4[i + 1];
        a0 = fmaf(w.x, s.x, a0);   a0 = fmaf(w.y, s.y, a0);
        a0 = fmaf(w.z, s.z, a0);   a0 = fmaf(w.w, s.w, a0);
        a1 = fmaf(w2.x, s2.x, a1); a1 = fmaf(w2.y, s2.y, a1);
        a1 = fmaf(w2.z, s2.z, a1); a1 = fmaf(w2.w, s2.w, a1);
    }
    float acc = a0 + a1;
    acc += __shfl_xor_sync(0xffffffffu, acc, 1);
    acc += __shfl_xor_sync(0xffffffffu, acc, 2);
    if (part == 0) {
        if (out < 16) g_bbuf[t * HV + out] = acc;
        else          g_abuf[t * HV + (out - 16)] = acc;
    }
}

// ---------------------------------------------------------------------------
// Causal depthwise conv (KSZ=4) + silu + per-head L2 norm + gates.
// ---------------------------------------------------------------------------
__global__ __launch_bounds__(512) void conv_gate_kernel(
    const float* __restrict__ conv_w,
    const float* __restrict__ dt_bias, const float* __restrict__ A_log,
    const int* __restrict__ cu, int nseq)
{
    const int t = blockIdx.x;
    __shared__ float ybuf[CONV_DIM];
    __shared__ float ssq[16];

    int start = 0;
    for (int b = 0; b < nseq; b++) {
        int s = cu[b];
        if (t >= s) start = s;
    }

#pragma unroll
    for (int r = 0; r < 4; r++) {
        int c = threadIdx.x + 512 * r;
        float acc = 0.f;
#pragma unroll
        for (int j = 0; j < 4; j++) {
            int tt = t - 3 + j;
            if (tt >= start)
                acc = fmaf(conv_w[c * 4 + j], g_mixed[(size_t)tt * CONV_DIM + c], acc);
        }
        ybuf[c] = acc / (1.f + expf(-acc));
    }
    __syncthreads();

    {
        int w = threadIdx.x >> 5, lane = threadIdx.x & 31;
        float x0 = ybuf[w * 64 + lane];
        float x1 = ybuf[w * 64 + 32 + lane];
        float s2 = x0 * x0 + x1 * x1;
#pragma unroll
        for (int off = 16; off > 0; off >>= 1)
            s2 += __shfl_xor_sync(0xffffffffu, s2, off);
        if (lane == 0) ssq[w] = s2;
    }
    __syncthreads();

#pragma unroll
    for (int r = 0; r < 4; r++) {
        int c = threadIdx.x + 512 * r;
        float yv = ybuf[c];
        if (c < KEY_DIM) {
            int h = c >> 6;
            g_qn[(size_t)t * KEY_DIM + c] = yv * rsqrtf(ssq[h] + 1e-6f) * 0.125f;
        } else if (c < 2 * KEY_DIM) {
            int cc = c - KEY_DIM;
            int h = cc >> 6;
            g_kn[(size_t)t * KEY_DIM + cc] = yv * rsqrtf(ssq[8 + h] + 1e-6f);
        } else {
            g_vv[(size_t)t * VAL_DIM + (c - 2 * KEY_DIM)] = yv;
        }
    }

    if (threadIdx.x < HV) {
        int h = threadIdx.x;
        float bb = g_bbuf[t * HV + h];
        g_beta[t * HV + h] = 1.f / (1.f + expf(-bb));
        float aa = g_abuf[t * HV + h] + dt_bias[h];
        float sp = (aa > 20.f) ? aa : log1pf(expf(aa));
        g_gate[t * HV + h] = -expf(A_log[h]) * sp;
    }
}

// ---------------------------------------------------------------------------
// Gated delta rule recurrence, f32x2 packed math.
// grid (HV, nseq, 2); 128 threads: column c = tid>>2, row-group r = tid&3.
// ---------------------------------------------------------------------------
__global__ __launch_bounds__(128) void delta_kernel(const int* __restrict__ cu)
{
    const int h  = blockIdx.x;
    const int b  = blockIdx.y;
    const int j  = blockIdx.z * 32 + (threadIdx.x >> 2);
    const int r  = threadIdx.x & 3;
    const int i0 = r * 16;
    const int kh = h >> 1;
    const int start = cu[b], end = cu[b + 1];

    unsigned long long S2[8];
#pragma unroll
    for (int i = 0; i < 8; i++) S2[i] = 0ULL;

    unsigned long long K2[8], Q2[8], Kn[8], Qn[8];
    float vc, gc, bc, vn, gn, bn;

    auto loadT = [&](int t, unsigned long long* kk, unsigned long long* qq,
                     float& v_, float& g_, float& b_) {
        const ulonglong2* kp = (const ulonglong2*)(g_kn + (size_t)t * KEY_DIM + kh * DK + i0);
        const ulonglong2* qp = (const ulonglong2*)(g_qn + (size_t)t * KEY_DIM + kh * DK + i0);
#pragma unroll
        for (int m = 0; m < 4; m++) {
            ulonglong2 ku = kp[m], qu = qp[m];
            kk[2 * m] = ku.x; kk[2 * m + 1] = ku.y;
            qq[2 * m] = qu.x; qq[2 * m + 1] = qu.y;
        }
        v_ = g_vv[(size_t)t * VAL_DIM + h * DV + j];
        g_ = g_gate[t * HV + h];
        b_ = g_beta[t * HV + h];
    };

    if (start < end) loadT(start, K2, Q2, vc, gc, bc);

    for (int t = start; t < end; t++) {
        int tn = (t + 1 < end) ? (t + 1) : t;
        loadT(tn, Kn, Qn, vn, gn, bn);

        const float dec = expf(gc);

        unsigned long long p0 = 0ULL, p1 = 0ULL;
#pragma unroll
        for (int m = 0; m < 8; m += 2) {
            p0 = fma2(K2[m],     S2[m],     p0);
            p1 = fma2(K2[m + 1], S2[m + 1], p1);
        }
        float lo0, hi0, lo1, hi1;
        upk2(p0, lo0, hi0); upk2(p1, lo1, hi1);
        float ks = (lo0 + hi0) + (lo1 + hi1);
        ks += __shfl_xor_sync(0xffffffffu, ks, 1);
        ks += __shfl_xor_sync(0xffffffffu, ks, 2);

        const float delta = bc * (vc - dec * ks);
        const unsigned long long d2 = pk2(delta, delta);
        const unsigned long long dc2 = pk2(dec, dec);

        unsigned long long o0 = 0ULL, o1 = 0ULL;
#pragma unroll
        for (int m = 0; m < 8; m += 2) {
            unsigned long long kd0 = mul2(K2[m], d2);
            unsigned long long kd1 = mul2(K2[m + 1], d2);
            S2[m]     = fma2(dc2, S2[m],     kd0);
            S2[m + 1] = fma2(dc2, S2[m + 1], kd1);
            o0 = fma2(Q2[m],     S2[m],     o0);
            o1 = fma2(Q2[m + 1], S2[m + 1], o1);
        }
        upk2(o0, lo0, hi0); upk2(o1, lo1, hi1);
        float oo = (lo0 + hi0) + (lo1 + hi1);
        oo += __shfl_xor_sync(0xffffffffu, oo, 1);
        oo += __shfl_xor_sync(0xffffffffu, oo, 2);
        if (r == 0) g_obuf[(size_t)t * VAL_DIM + h * DV + j] = oo;

#pragma unroll
        for (int m = 0; m < 8; m++) { K2[m] = Kn[m]; Q2[m] = Qn[m]; }
        vc = vn; gc = gn; bc = bn;
    }
}

// ---------------------------------------------------------------------------
// Gated RMSNorm: o * rsqrt(mean(o^2)+eps) * norm_weight * silu(z)
// ---------------------------------------------------------------------------
__global__ __launch_bounds__(256) void gated_norm_kernel(const float* __restrict__ nw)
{
    const int t = blockIdx.x;
    const int tid = threadIdx.x;
    const int h = tid >> 4;
    const int s = tid & 15;

    const size_t base = ((size_t)t * HV + h) * DV + s * 4;
    float4 o4 = *(const float4*)(g_obuf + base);
    float ss = o4.x * o4.x + o4.y * o4.y + o4.z * o4.z + o4.w * o4.w;
    ss += __shfl_xor_sync(0xffffffffu, ss, 8);
    ss += __shfl_xor_sync(0xffffffffu, ss, 4);
    ss += __shfl_xor_sync(0xffffffffu, ss, 2);
    ss += __shfl_xor_sync(0xffffffffu, ss, 1);
    const float rr = rsqrtf(ss * (1.f / 64.f) + 1e-6f);

    float4 z4 = *(const float4*)(g_zbuf + (size_t)t * VAL_DIM + h * DV + s * 4);
    float4 w4 = *(const float4*)(nw + s * 4);
    float4 out;
    out.x = o4.x * rr * w4.x * (z4.x / (1.f + expf(-z4.x)));
    out.y = o4.y * rr * w4.y * (z4.y / (1.f + expf(-z4.y)));
    out.z = o4.z * rr * w4.z * (z4.z / (1.f + expf(-z4.z)));
    out.w = o4.w * rr * w4.w * (z4.w / (1.f + expf(-z4.w)));
    *(float4*)(g_onrm + base) = out;
}

// ---------------------------------------------------------------------------
extern "C" void kernel_launch(void* const* d_in, const int* in_sizes, int n_in,
                              void* d_out, int out_size)
{
    const float* hidden  = (const float*)d_in[0];
    const float* W_qkv   = (const float*)d_in[1];
    const float* W_z     = (const float*)d_in[2];
    const float* W_b     = (const float*)d_in[3];
    const float* W_a     = (const float*)d_in[4];
    const float* conv_w  = (const float*)d_in[5];
    const float* dt_bias = (const float*)d_in[6];
    const float* A_log   = (const float*)d_in[7];
    const float* nw      = (const float*)d_in[8];
    const float* W_out   = (const float*)d_in[9];
    const int*   cu      = (const int*)d_in[10];

    const int total = in_sizes[0] / HIDDEN;
    const int nseq  = in_sizes[10] - 1;

    float *mixed, *zb, *on;
    cudaGetSymbolAddress((void**)&mixed, g_mixed);
    cudaGetSymbolAddress((void**)&zb,    g_zbuf);
    cudaGetSymbolAddress((void**)&on,    g_onrm);

    const int mB = (total + 127) / 128;

    // 1. big projections (tf32 tensor cores)
    gemm_tf32<<<dim3(CONV_DIM / 64, mB), 256>>>(hidden, W_qkv, mixed, total, CONV_DIM, HIDDEN);
    gemm_tf32<<<dim3(VAL_DIM / 64,  mB), 256>>>(hidden, W_z,   zb,    total, VAL_DIM,  HIDDEN);

    // 2. small projections (b, a fused)
    small_proj_kernel<<<total, 128>>>(hidden, W_b, W_a);

    // 3. conv + silu + norms + gates
    conv_gate_kernel<<<total, 512>>>(conv_w, dt_bias, A_log, cu, nseq);

    // 4. recurrence
    delta_kernel<<<dim3(HV, nseq, 2), 128>>>(cu);

    // 5. gated RMSNorm
    gated_norm_kernel<<<total, 256>>>(nw);

    // 6. output projection
    gemm_tf32<<<dim3(VAL_DIM / 64, mB), 256>>>(on, W_out, (float*)d_out, total, HIDDEN, HIDDEN);
}

// round 7
// speedup vs baseline: 1.8415x; 1.0118x over previous
#include <cuda_runtime.h>
#include <cuda_bf16.h>
#include <math.h>
#include <stdint.h>

// ---------------------------------------------------------------------------
// GatedDeltaNetVarlen  (total=1536, HIDDEN=1024, HK=8, HV=16, DK=DV=64, KSZ=4)
// R7: mma.sync tf32 GEMM (sm_103 target lacks tcgen05!) with PRE-ROUNDED
// inputs -> zero cvt in the GEMM hot loop (R4 was cvt-bound).
// ---------------------------------------------------------------------------

#define TOTAL_MAX 1536
#define HIDDEN 1024
#define HK 8
#define HV 16
#define DK 64
#define DV 64
#define KEY_DIM 512
#define VAL_DIM 1024
#define CONV_DIM 2048

__device__ __align__(16) float g_mixed[TOTAL_MAX * CONV_DIM];
__device__ __align__(16) float g_zbuf [TOTAL_MAX * VAL_DIM];
__device__ __align__(16) float g_bbuf [TOTAL_MAX * HV];
__device__ __align__(16) float g_abuf [TOTAL_MAX * HV];
__device__ __align__(16) float g_qn   [TOTAL_MAX * KEY_DIM];
__device__ __align__(16) float g_kn   [TOTAL_MAX * KEY_DIM];
__device__ __align__(16) float g_vv   [TOTAL_MAX * VAL_DIM];
__device__ __align__(16) float g_beta [TOTAL_MAX * HV];
__device__ __align__(16) float g_gate [TOTAL_MAX * HV];
__device__ __align__(16) float g_obuf [TOTAL_MAX * VAL_DIM];
__device__ __align__(16) float g_onrm [TOTAL_MAX * VAL_DIM];
// tf32-rounded copies (bit patterns valid as mma.sync tf32 operands)
__device__ __align__(16) float g_hid_r [TOTAL_MAX * HIDDEN];
__device__ __align__(16) float g_wqkv_r[CONV_DIM * HIDDEN];
__device__ __align__(16) float g_wz_r  [VAL_DIM * HIDDEN];
__device__ __align__(16) float g_wout_r[HIDDEN * VAL_DIM];

// ------------------------------ helpers ------------------------------------
__device__ __forceinline__ unsigned f2tf32(float x) {
    unsigned u;
    asm("cvt.rna.tf32.f32 %0, %1;" : "=r"(u) : "f"(x));
    return u;
}
__device__ __forceinline__ float tf32r(float x) { return __uint_as_float(f2tf32(x)); }

__device__ __forceinline__ unsigned long long pk2(float a, float b) {
    unsigned long long r;
    asm("mov.b64 %0, {%1,%2};" : "=l"(r) : "f"(a), "f"(b));
    return r;
}
__device__ __forceinline__ void upk2(unsigned long long v, float& a, float& b) {
    asm("mov.b64 {%0,%1}, %2;" : "=f"(a), "=f"(b) : "l"(v));
}
__device__ __forceinline__ unsigned long long fma2(
    unsigned long long a, unsigned long long b, unsigned long long c) {
    unsigned long long d;
    asm("fma.rn.f32x2 %0, %1, %2, %3;" : "=l"(d) : "l"(a), "l"(b), "l"(c));
    return d;
}
__device__ __forceinline__ unsigned long long mul2(
    unsigned long long a, unsigned long long b) {
    unsigned long long d;
    asm("mul.rn.f32x2 %0, %1, %2;" : "=l"(d) : "l"(a), "l"(b));
    return d;
}

// ---------------------------------------------------------------------------
// tf32 rounding pre-pass (vectorized)
// ---------------------------------------------------------------------------
__global__ __launch_bounds__(256) void round_tf32_kernel(
    const float4* __restrict__ s, float4* __restrict__ d, int n4)
{
    int i = blockIdx.x * blockDim.x + threadIdx.x;
    if (i < n4) {
        float4 v = s[i];
        v.x = tf32r(v.x); v.y = tf32r(v.y); v.z = tf32r(v.z); v.w = tf32r(v.w);
        d[i] = v;
    }
}

// ---------------------------------------------------------------------------
// tf32 mma.sync GEMM:  C[M,N] = A[M,K] * B[N,K]^T  (A,B pre-rounded to tf32).
// 256 threads (8 warps 4m x 2n), BM=128, BN=64, BK=32, warp tile 32x32.
// No cvt in the loop: stage raw bits. Smem [m][k] pitch 36 (conflict-free).
// ---------------------------------------------------------------------------
#define PAD 36

__global__ __launch_bounds__(256) void gemm_tf32(
    const float* __restrict__ A, const float* __restrict__ B,
    float* __restrict__ C, int M, int N, int K)
{
    __shared__ unsigned As[128 * PAD];
    __shared__ unsigned Bs[64 * PAD];

    const int tid  = threadIdx.x;
    const int lane = tid & 31;
    const int wid  = tid >> 5;
    const int wm   = wid >> 1;        // 0..3
    const int wn   = wid & 1;         // 0..1
    const int gid  = lane >> 2;       // 0..7
    const int tig  = lane & 3;        // 0..3

    const int m0 = blockIdx.y * 128;
    const int n0 = blockIdx.x * 64;

    const int srow = tid >> 3;            // 0..31
    const int scol = (tid & 7) << 2;      // 0,4,...,28

    float acc[2][4][4];
#pragma unroll
    for (int i = 0; i < 2; i++)
#pragma unroll
        for (int j = 0; j < 4; j++)
#pragma unroll
            for (int v = 0; v < 4; v++) acc[i][j][v] = 0.f;

    const int iters = K / 32;
    uint4 Ar[4], Br[2];
    const uint4 z4 = make_uint4(0u, 0u, 0u, 0u);

    // prefetch iter 0 (coalesced: 8 threads per row)
#pragma unroll
    for (int p = 0; p < 4; p++) {
        int r = srow + 32 * p;
        Ar[p] = (m0 + r < M) ? *(const uint4*)(A + (size_t)(m0 + r) * K + scol) : z4;
    }
#pragma unroll
    for (int p = 0; p < 2; p++) {
        int r = srow + 32 * p;
        Br[p] = (n0 + r < N) ? *(const uint4*)(B + (size_t)(n0 + r) * K + scol) : z4;
    }

    for (int it = 0; it < iters; it++) {
        if (it > 0) __syncthreads();

#pragma unroll
        for (int p = 0; p < 4; p++)
            *(uint4*)&As[(srow + 32 * p) * PAD + scol] = Ar[p];
#pragma unroll
        for (int p = 0; p < 2; p++)
            *(uint4*)&Bs[(srow + 32 * p) * PAD + scol] = Br[p];
        __syncthreads();

        if (it + 1 < iters) {
            int k0 = (it + 1) * 32;
#pragma unroll
            for (int p = 0; p < 4; p++) {
                int r = srow + 32 * p;
                Ar[p] = (m0 + r < M) ? *(const uint4*)(A + (size_t)(m0 + r) * K + k0 + scol) : z4;
            }
#pragma unroll
            for (int p = 0; p < 2; p++) {
                int r = srow + 32 * p;
                Br[p] = (n0 + r < N) ? *(const uint4*)(B + (size_t)(n0 + r) * K + k0 + scol) : z4;
            }
        }

#pragma unroll
        for (int s = 0; s < 4; s++) {
            const int ks = s * 8;
            unsigned af[2][4], bf[4][2];
#pragma unroll
            for (int mt = 0; mt < 2; mt++) {
                int mr = wm * 32 + mt * 16 + gid;
                af[mt][0] = As[mr * PAD + ks + tig];
                af[mt][1] = As[(mr + 8) * PAD + ks + tig];
                af[mt][2] = As[mr * PAD + ks + tig + 4];
                af[mt][3] = As[(mr + 8) * PAD + ks + tig + 4];
            }
#pragma unroll
            for (int nt = 0; nt < 4; nt++) {
                int nr = wn * 32 + nt * 8 + gid;
                bf[nt][0] = Bs[nr * PAD + ks + tig];
                bf[nt][1] = Bs[nr * PAD + ks + tig + 4];
            }
#pragma unroll
            for (int mt = 0; mt < 2; mt++)
#pragma unroll
                for (int nt = 0; nt < 4; nt++) {
                    asm volatile(
                        "mma.sync.aligned.m16n8k8.row.col.f32.tf32.tf32.f32 "
                        "{%0,%1,%2,%3}, {%4,%5,%6,%7}, {%8,%9}, {%0,%1,%2,%3};"
                        : "+f"(acc[mt][nt][0]), "+f"(acc[mt][nt][1]),
                          "+f"(acc[mt][nt][2]), "+f"(acc[mt][nt][3])
                        : "r"(af[mt][0]), "r"(af[mt][1]), "r"(af[mt][2]), "r"(af[mt][3]),
                          "r"(bf[nt][0]), "r"(bf[nt][1]));
                }
        }
    }

    // epilogue
#pragma unroll
    for (int mt = 0; mt < 2; mt++) {
        int row = m0 + wm * 32 + mt * 16 + gid;
#pragma unroll
        for (int nt = 0; nt < 4; nt++) {
            int col = n0 + wn * 32 + nt * 8 + tig * 2;
            if (row < M)
                *(float2*)(C + (size_t)row * N + col) =
                    make_float2(acc[mt][nt][0], acc[mt][nt][1]);
            if (row + 8 < M)
                *(float2*)(C + (size_t)(row + 8) * N + col) =
                    make_float2(acc[mt][nt][2], acc[mt][nt][3]);
        }
    }
}

// ---------------------------------------------------------------------------
// Fused small projections: b = h@W_b^T, a = h@W_a^T  (N=16 each).
// ---------------------------------------------------------------------------
__global__ __launch_bounds__(128) void small_proj_kernel(
    const float* __restrict__ hs,
    const float* __restrict__ W_b, const float* __restrict__ W_a)
{
    const int t = blockIdx.x;
    __shared__ float sh[HIDDEN];
    {
        const float4* hp = (const float4*)(hs + (size_t)t * HIDDEN);
        float4* sp = (float4*)sh;
        sp[threadIdx.x]       = hp[threadIdx.x];
        sp[threadIdx.x + 128] = hp[threadIdx.x + 128];
    }
    __syncthreads();

    const int out  = threadIdx.x >> 2;
    const int part = threadIdx.x & 3;
    const float* W = (out < 16) ? (W_b + (size_t)out * HIDDEN)
                                : (W_a + (size_t)(out - 16) * HIDDEN);
    const float4* W4 = (const float4*)(W + part * 256);
    const float4* S4 = (const float4*)(sh + part * 256);

    float a0 = 0.f, a1 = 0.f;
#pragma unroll 8
    for (int i = 0; i < 64; i += 2) {
        float4 w = W4[i],      s = S4[i];
        float4 w2 = W4[i + 1], s2 = S4[i + 1];
        a0 = fmaf(w.x, s.x, a0);   a0 = fmaf(w.y, s.y, a0);
        a0 = fmaf(w.z, s.z, a0);   a0 = fmaf(w.w, s.w, a0);
        a1 = fmaf(w2.x, s2.x, a1); a1 = fmaf(w2.y, s2.y, a1);
        a1 = fmaf(w2.z, s2.z, a1); a1 = fmaf(w2.w, s2.w, a1);
    }
    float acc = a0 + a1;
    acc += __shfl_xor_sync(0xffffffffu, acc, 1);
    acc += __shfl_xor_sync(0xffffffffu, acc, 2);
    if (part == 0) {
        if (out < 16) g_bbuf[t * HV + out] = acc;
        else          g_abuf[t * HV + (out - 16)] = acc;
    }
}

// ---------------------------------------------------------------------------
// Causal depthwise conv (KSZ=4) + silu + per-head L2 norm + gates.
// ---------------------------------------------------------------------------
__global__ __launch_bounds__(512) void conv_gate_kernel(
    const float* __restrict__ conv_w,
    const float* __restrict__ dt_bias, const float* __restrict__ A_log,
    const int* __restrict__ cu, int nseq)
{
    const int t = blockIdx.x;
    __shared__ float ybuf[CONV_DIM];
    __shared__ float ssq[16];

    int start = 0;
    for (int b = 0; b < nseq; b++) {
        int s = cu[b];
        if (t >= s) start = s;
    }

#pragma unroll
    for (int r = 0; r < 4; r++) {
        int c = threadIdx.x + 512 * r;
        float acc = 0.f;
#pragma unroll
        for (int j = 0; j < 4; j++) {
            int tt = t - 3 + j;
            if (tt >= start)
                acc = fmaf(conv_w[c * 4 + j], g_mixed[(size_t)tt * CONV_DIM + c], acc);
        }
        ybuf[c] = acc / (1.f + expf(-acc));
    }
    __syncthreads();

    {
        int w = threadIdx.x >> 5, lane = threadIdx.x & 31;
        float x0 = ybuf[w * 64 + lane];
        float x1 = ybuf[w * 64 + 32 + lane];
        float s2 = x0 * x0 + x1 * x1;
#pragma unroll
        for (int off = 16; off > 0; off >>= 1)
            s2 += __shfl_xor_sync(0xffffffffu, s2, off);
        if (lane == 0) ssq[w] = s2;
    }
    __syncthreads();

#pragma unroll
    for (int r = 0; r < 4; r++) {
        int c = threadIdx.x + 512 * r;
        float yv = ybuf[c];
        if (c < KEY_DIM) {
            int h = c >> 6;
            g_qn[(size_t)t * KEY_DIM + c] = yv * rsqrtf(ssq[h] + 1e-6f) * 0.125f;
        } else if (c < 2 * KEY_DIM) {
            int cc = c - KEY_DIM;
            int h = cc >> 6;
            g_kn[(size_t)t * KEY_DIM + cc] = yv * rsqrtf(ssq[8 + h] + 1e-6f);
        } else {
            g_vv[(size_t)t * VAL_DIM + (c - 2 * KEY_DIM)] = yv;
        }
    }

    if (threadIdx.x < HV) {
        int h = threadIdx.x;
        float bb = g_bbuf[t * HV + h];
        g_beta[t * HV + h] = 1.f / (1.f + expf(-bb));
        float aa = g_abuf[t * HV + h] + dt_bias[h];
        float sp = (aa > 20.f) ? aa : log1pf(expf(aa));
        g_gate[t * HV + h] = -expf(A_log[h]) * sp;
    }
}

// ---------------------------------------------------------------------------
// Gated delta rule recurrence, f32x2 packed math.
// grid (HV, nseq, 2); 128 threads: column c = tid>>2, row-group r = tid&3.
// ---------------------------------------------------------------------------
__global__ __launch_bounds__(128) void delta_kernel(const int* __restrict__ cu)
{
    const int h  = blockIdx.x;
    const int b  = blockIdx.y;
    const int j  = blockIdx.z * 32 + (threadIdx.x >> 2);
    const int r  = threadIdx.x & 3;
    const int i0 = r * 16;
    const int kh = h >> 1;
    const int start = cu[b], end = cu[b + 1];

    unsigned long long S2[8];
#pragma unroll
    for (int i = 0; i < 8; i++) S2[i] = 0ULL;

    unsigned long long K2[8], Q2[8], Kn[8], Qn[8];
    float vc, gc, bc, vn, gn, bn;

    auto loadT = [&](int t, unsigned long long* kk, unsigned long long* qq,
                     float& v_, float& g_, float& b_) {
        const ulonglong2* kp = (const ulonglong2*)(g_kn + (size_t)t * KEY_DIM + kh * DK + i0);
        const ulonglong2* qp = (const ulonglong2*)(g_qn + (size_t)t * KEY_DIM + kh * DK + i0);
#pragma unroll
        for (int m = 0; m < 4; m++) {
            ulonglong2 ku = kp[m], qu = qp[m];
            kk[2 * m] = ku.x; kk[2 * m + 1] = ku.y;
            qq[2 * m] = qu.x; qq[2 * m + 1] = qu.y;
        }
        v_ = g_vv[(size_t)t * VAL_DIM + h * DV + j];
        g_ = g_gate[t * HV + h];
        b_ = g_beta[t * HV + h];
    };

    if (start < end) loadT(start, K2, Q2, vc, gc, bc);

    for (int t = start; t < end; t++) {
        int tn = (t + 1 < end) ? (t + 1) : t;
        loadT(tn, Kn, Qn, vn, gn, bn);

        const float dec = expf(gc);

        unsigned long long p0 = 0ULL, p1 = 0ULL;
#pragma unroll
        for (int m = 0; m < 8; m += 2) {
            p0 = fma2(K2[m],     S2[m],     p0);
            p1 = fma2(K2[m + 1], S2[m + 1], p1);
        }
        float lo0, hi0, lo1, hi1;
        upk2(p0, lo0, hi0); upk2(p1, lo1, hi1);
        float ks = (lo0 + hi0) + (lo1 + hi1);
        ks += __shfl_xor_sync(0xffffffffu, ks, 1);
        ks += __shfl_xor_sync(0xffffffffu, ks, 2);

        const float delta = bc * (vc - dec * ks);
        const unsigned long long d2 = pk2(delta, delta);
        const unsigned long long dc2 = pk2(dec, dec);

        unsigned long long o0 = 0ULL, o1 = 0ULL;
#pragma unroll
        for (int m = 0; m < 8; m += 2) {
            unsigned long long kd0 = mul2(K2[m], d2);
            unsigned long long kd1 = mul2(K2[m + 1], d2);
            S2[m]     = fma2(dc2, S2[m],     kd0);
            S2[m + 1] = fma2(dc2, S2[m + 1], kd1);
            o0 = fma2(Q2[m],     S2[m],     o0);
            o1 = fma2(Q2[m + 1], S2[m + 1], o1);
        }
        upk2(o0, lo0, hi0); upk2(o1, lo1, hi1);
        float oo = (lo0 + hi0) + (lo1 + hi1);
        oo += __shfl_xor_sync(0xffffffffu, oo, 1);
        oo += __shfl_xor_sync(0xffffffffu, oo, 2);
        if (r == 0) g_obuf[(size_t)t * VAL_DIM + h * DV + j] = oo;

#pragma unroll
        for (int m = 0; m < 8; m++) { K2[m] = Kn[m]; Q2[m] = Qn[m]; }
        vc = vn; gc = gn; bc = bn;
    }
}

// ---------------------------------------------------------------------------
// Gated RMSNorm; output stored tf32-rounded (feeds the out-projection GEMM).
// ---------------------------------------------------------------------------
__global__ __launch_bounds__(256) void gated_norm_kernel(const float* __restrict__ nw)
{
    const int t = blockIdx.x;
    const int tid = threadIdx.x;
    const int h = tid >> 4;
    const int s = tid & 15;

    const size_t base = ((size_t)t * HV + h) * DV + s * 4;
    float4 o4 = *(const float4*)(g_obuf + base);
    float ss = o4.x * o4.x + o4.y * o4.y + o4.z * o4.z + o4.w * o4.w;
    ss += __shfl_xor_sync(0xffffffffu, ss, 8);
    ss += __shfl_xor_sync(0xffffffffu, ss, 4);
    ss += __shfl_xor_sync(0xffffffffu, ss, 2);
    ss += __shfl_xor_sync(0xffffffffu, ss, 1);
    const float rr = rsqrtf(ss * (1.f / 64.f) + 1e-6f);

    float4 z4 = *(const float4*)(g_zbuf + (size_t)t * VAL_DIM + h * DV + s * 4);
    float4 w4 = *(const float4*)(nw + s * 4);
    float4 out;
    out.x = tf32r(o4.x * rr * w4.x * (z4.x / (1.f + expf(-z4.x))));
    out.y = tf32r(o4.y * rr * w4.y * (z4.y / (1.f + expf(-z4.y))));
    out.z = tf32r(o4.z * rr * w4.z * (z4.z / (1.f + expf(-z4.z))));
    out.w = tf32r(o4.w * rr * w4.w * (z4.w / (1.f + expf(-z4.w))));
    *(float4*)(g_onrm + base) = out;
}

// ---------------------------------------------------------------------------
extern "C" void kernel_launch(void* const* d_in, const int* in_sizes, int n_in,
                              void* d_out, int out_size)
{
    const float* hidden  = (const float*)d_in[0];
    const float* W_qkv   = (const float*)d_in[1];
    const float* W_z     = (const float*)d_in[2];
    const float* W_b     = (const float*)d_in[3];
    const float* W_a     = (const float*)d_in[4];
    const float* conv_w  = (const float*)d_in[5];
    const float* dt_bias = (const float*)d_in[6];
    const float* A_log   = (const float*)d_in[7];
    const float* nw      = (const float*)d_in[8];
    const float* W_out   = (const float*)d_in[9];
    const int*   cu      = (const int*)d_in[10];

    const int total = in_sizes[0] / HIDDEN;
    const int nseq  = in_sizes[10] - 1;

    float *mixed, *zb, *on, *hidr, *wqkvr, *wzr, *woutr;
    cudaGetSymbolAddress((void**)&mixed, g_mixed);
    cudaGetSymbolAddress((void**)&zb,    g_zbuf);
    cudaGetSymbolAddress((void**)&on,    g_onrm);
    cudaGetSymbolAddress((void**)&hidr,  g_hid_r);
    cudaGetSymbolAddress((void**)&wqkvr, g_wqkv_r);
    cudaGetSymbolAddress((void**)&wzr,   g_wz_r);
    cudaGetSymbolAddress((void**)&woutr, g_wout_r);

    // 0. tf32 rounding pre-pass
    {
        int n4;
        n4 = total * HIDDEN / 4;
        round_tf32_kernel<<<(n4 + 255) / 256, 256>>>((const float4*)hidden, (float4*)hidr, n4);
        n4 = CONV_DIM * HIDDEN / 4;
        round_tf32_kernel<<<(n4 + 255) / 256, 256>>>((const float4*)W_qkv, (float4*)wqkvr, n4);
        n4 = VAL_DIM * HIDDEN / 4;
        round_tf32_kernel<<<(n4 + 255) / 256, 256>>>((const float4*)W_z, (float4*)wzr, n4);
        n4 = HIDDEN * VAL_DIM / 4;
        round_tf32_kernel<<<(n4 + 255) / 256, 256>>>((const float4*)W_out, (float4*)woutr, n4);
    }

    const int mB = (total + 127) / 128;

    // 1. big projections (tf32 tensor cores, no cvt in loop)
    gemm_tf32<<<dim3(CONV_DIM / 64, mB), 256>>>(hidr, wqkvr, mixed, total, CONV_DIM, HIDDEN);
    gemm_tf32<<<dim3(VAL_DIM / 64,  mB), 256>>>(hidr, wzr,   zb,    total, VAL_DIM,  HIDDEN);

    // 2. small projections (b, a fused)
    small_proj_kernel<<<total, 128>>>(hidden, W_b, W_a);

    // 3. conv + silu + norms + gates
    conv_gate_kernel<<<total, 512>>>(conv_w, dt_bias, A_log, cu, nseq);

    // 4. recurrence
    delta_kernel<<<dim3(HV, nseq, 2), 128>>>(cu);

    // 5. gated RMSNorm (tf32-rounded output)
    gated_norm_kernel<<<total, 256>>>(nw);

    // 6. output projection
    gemm_tf32<<<dim3(VAL_DIM / 64, mB), 256>>>(on, woutr, (float*)d_out, total, HIDDEN, HIDDEN);
}

// round 8
// speedup vs baseline: 1.8633x; 1.0118x over previous
#include <cuda_runtime.h>
#include <cuda_bf16.h>
#include <math.h>
#include <stdint.h>

// ---------------------------------------------------------------------------
// GatedDeltaNetVarlen  (total=1536, HIDDEN=1024, HK=8, HV=16, DK=DV=64, KSZ=4)
// R8: cp.async 3-stage pipelined tf32 mma GEMM (R7 was latency/sync-exposed,
// not cvt-bound: 63 cyc/HMMA measured). Same math order as R7.
// ---------------------------------------------------------------------------

#define TOTAL_MAX 1536
#define HIDDEN 1024
#define HK 8
#define HV 16
#define DK 64
#define DV 64
#define KEY_DIM 512
#define VAL_DIM 1024
#define CONV_DIM 2048

__device__ __align__(16) float g_mixed[TOTAL_MAX * CONV_DIM];
__device__ __align__(16) float g_zbuf [TOTAL_MAX * VAL_DIM];
__device__ __align__(16) float g_bbuf [TOTAL_MAX * HV];
__device__ __align__(16) float g_abuf [TOTAL_MAX * HV];
__device__ __align__(16) float g_qn   [TOTAL_MAX * KEY_DIM];
__device__ __align__(16) float g_kn   [TOTAL_MAX * KEY_DIM];
__device__ __align__(16) float g_vv   [TOTAL_MAX * VAL_DIM];
__device__ __align__(16) float g_beta [TOTAL_MAX * HV];
__device__ __align__(16) float g_gate [TOTAL_MAX * HV];
__device__ __align__(16) float g_obuf [TOTAL_MAX * VAL_DIM];
__device__ __align__(16) float g_onrm [TOTAL_MAX * VAL_DIM];
// tf32-rounded copies (bit patterns valid as mma.sync tf32 operands)
__device__ __align__(16) float g_hid_r [TOTAL_MAX * HIDDEN];
__device__ __align__(16) float g_wqkv_r[CONV_DIM * HIDDEN];
__device__ __align__(16) float g_wz_r  [VAL_DIM * HIDDEN];
__device__ __align__(16) float g_wout_r[HIDDEN * VAL_DIM];

// ------------------------------ helpers ------------------------------------
__device__ __forceinline__ unsigned f2tf32(float x) {
    unsigned u;
    asm("cvt.rna.tf32.f32 %0, %1;" : "=r"(u) : "f"(x));
    return u;
}
__device__ __forceinline__ float tf32r(float x) { return __uint_as_float(f2tf32(x)); }

__device__ __forceinline__ unsigned long long pk2(float a, float b) {
    unsigned long long r;
    asm("mov.b64 %0, {%1,%2};" : "=l"(r) : "f"(a), "f"(b));
    return r;
}
__device__ __forceinline__ void upk2(unsigned long long v, float& a, float& b) {
    asm("mov.b64 {%0,%1}, %2;" : "=f"(a), "=f"(b) : "l"(v));
}
__device__ __forceinline__ unsigned long long fma2(
    unsigned long long a, unsigned long long b, unsigned long long c) {
    unsigned long long d;
    asm("fma.rn.f32x2 %0, %1, %2, %3;" : "=l"(d) : "l"(a), "l"(b), "l"(c));
    return d;
}
__device__ __forceinline__ unsigned long long mul2(
    unsigned long long a, unsigned long long b) {
    unsigned long long d;
    asm("mul.rn.f32x2 %0, %1, %2;" : "=l"(d) : "l"(a), "l"(b));
    return d;
}
__device__ __forceinline__ void cpa16(uint32_t dst, const void* src, bool ok) {
    int sz = ok ? 16 : 0;
    asm volatile("cp.async.cg.shared.global [%0], [%1], 16, %2;"
                 :: "r"(dst), "l"(src), "r"(sz) : "memory");
}

// ---------------------------------------------------------------------------
// tf32 rounding pre-pass (vectorized)
// ---------------------------------------------------------------------------
__global__ __launch_bounds__(256) void round_tf32_kernel(
    const float4* __restrict__ s, float4* __restrict__ d, int n4)
{
    int i = blockIdx.x * blockDim.x + threadIdx.x;
    if (i < n4) {
        float4 v = s[i];
        v.x = tf32r(v.x); v.y = tf32r(v.y); v.z = tf32r(v.z); v.w = tf32r(v.w);
        d[i] = v;
    }
}

// ---------------------------------------------------------------------------
// tf32 mma.sync GEMM:  C[M,N] = A[M,K] * B[N,K]^T  (A,B pre-rounded tf32).
// 256 threads (8 warps 4m x 2n), BM=128, BN=64, BK=32, warp tile 32x32.
// cp.async 3-stage pipeline: global->smem direct, one sync per iter.
// Smem [m][k] pitch 36 words: fragment reads bank = 4*gid+tig, conflict-free.
// ---------------------------------------------------------------------------
#define PAD 36
#define STG 3
#define A_WORDS (128 * PAD)
#define B_WORDS (64 * PAD)
#define SMEM_WORDS (STG * (A_WORDS + B_WORDS))

__global__ __launch_bounds__(256) void gemm_tf32(
    const float* __restrict__ A, const float* __restrict__ B,
    float* __restrict__ C, int M, int N, int K)
{
    extern __shared__ unsigned shm[];
    const uint32_t sb = (uint32_t)__cvta_generic_to_shared(shm);

    const int tid  = threadIdx.x;
    const int lane = tid & 31;
    const int wid  = tid >> 5;
    const int wm   = wid >> 1;        // 0..3
    const int wn   = wid & 1;         // 0..1
    const int gid  = lane >> 2;       // 0..7
    const int tig  = lane & 3;        // 0..3

    const int m0 = blockIdx.y * 128;
    const int n0 = blockIdx.x * 64;

    const int srow = tid >> 3;            // 0..31
    const int scol = (tid & 7) << 2;      // word col 0,4,...,28

    const int iters = K / 32;

    // issue one K-block stage (or an empty commit past the end)
    auto stage_in = [&](int it) {
        if (it < iters) {
            const int s  = it % STG;
            const int k0 = it * 32;
            const uint32_t sA = sb + (s * A_WORDS) * 4;
            const uint32_t sB = sb + (STG * A_WORDS + s * B_WORDS) * 4;
#pragma unroll
            for (int p = 0; p < 4; p++) {
                int r = srow + 32 * p;
                cpa16(sA + ((r * PAD + scol) << 2),
                      A + (size_t)(m0 + r) * K + k0 + scol, (m0 + r) < M);
            }
#pragma unroll
            for (int p = 0; p < 2; p++) {
                int r = srow + 32 * p;
                cpa16(sB + ((r * PAD + scol) << 2),
                      B + (size_t)(n0 + r) * K + k0 + scol, (n0 + r) < N);
            }
        }
        asm volatile("cp.async.commit_group;" ::: "memory");
    };

    float acc[2][4][4];
#pragma unroll
    for (int i = 0; i < 2; i++)
#pragma unroll
        for (int j = 0; j < 4; j++)
#pragma unroll
            for (int v = 0; v < 4; v++) acc[i][j][v] = 0.f;

    stage_in(0);
    stage_in(1);

    for (int it = 0; it < iters; it++) {
        asm volatile("cp.async.wait_group 1;" ::: "memory");
        __syncthreads();          // stage 'it' visible to all; iter it-1 reads done
        stage_in(it + 2);         // overwrites buffer read at iter it-1 (safe)

        const int s = it % STG;
        const unsigned* As = shm + s * A_WORDS;
        const unsigned* Bs = shm + STG * A_WORDS + s * B_WORDS;

#pragma unroll
        for (int ss = 0; ss < 4; ss++) {
            const int ks = ss * 8;
            unsigned af[2][4], bf[4][2];
#pragma unroll
            for (int mt = 0; mt < 2; mt++) {
                int mr = wm * 32 + mt * 16 + gid;
                af[mt][0] = As[mr * PAD + ks + tig];
                af[mt][1] = As[(mr + 8) * PAD + ks + tig];
                af[mt][2] = As[mr * PAD + ks + tig + 4];
                af[mt][3] = As[(mr + 8) * PAD + ks + tig + 4];
            }
#pragma unroll
            for (int nt = 0; nt < 4; nt++) {
                int nr = wn * 32 + nt * 8 + gid;
                bf[nt][0] = Bs[nr * PAD + ks + tig];
                bf[nt][1] = Bs[nr * PAD + ks + tig + 4];
            }
#pragma unroll
            for (int mt = 0; mt < 2; mt++)
#pragma unroll
                for (int nt = 0; nt < 4; nt++) {
                    asm volatile(
                        "mma.sync.aligned.m16n8k8.row.col.f32.tf32.tf32.f32 "
                        "{%0,%1,%2,%3}, {%4,%5,%6,%7}, {%8,%9}, {%0,%1,%2,%3};"
                        : "+f"(acc[mt][nt][0]), "+f"(acc[mt][nt][1]),
                          "+f"(acc[mt][nt][2]), "+f"(acc[mt][nt][3])
                        : "r"(af[mt][0]), "r"(af[mt][1]), "r"(af[mt][2]), "r"(af[mt][3]),
                          "r"(bf[nt][0]), "r"(bf[nt][1]));
                }
        }
    }

    // epilogue
#pragma unroll
    for (int mt = 0; mt < 2; mt++) {
        int row = m0 + wm * 32 + mt * 16 + gid;
#pragma unroll
        for (int nt = 0; nt < 4; nt++) {
            int col = n0 + wn * 32 + nt * 8 + tig * 2;
            if (row < M)
                *(float2*)(C + (size_t)row * N + col) =
                    make_float2(acc[mt][nt][0], acc[mt][nt][1]);
            if (row + 8 < M)
                *(float2*)(C + (size_t)(row + 8) * N + col) =
                    make_float2(acc[mt][nt][2], acc[mt][nt][3]);
        }
    }
}

// ---------------------------------------------------------------------------
// Fused small projections: b = h@W_b^T, a = h@W_a^T  (N=16 each).
// ---------------------------------------------------------------------------
__global__ __launch_bounds__(128) void small_proj_kernel(
    const float* __restrict__ hs,
    const float* __restrict__ W_b, const float* __restrict__ W_a)
{
    const int t = blockIdx.x;
    __shared__ float sh[HIDDEN];
    {
        const float4* hp = (const float4*)(hs + (size_t)t * HIDDEN);
        float4* sp = (float4*)sh;
        sp[threadIdx.x]       = hp[threadIdx.x];
        sp[threadIdx.x + 128] = hp[threadIdx.x + 128];
    }
    __syncthreads();

    const int out  = threadIdx.x >> 2;
    const int part = threadIdx.x & 3;
    const float* W = (out < 16) ? (W_b + (size_t)out * HIDDEN)
                                : (W_a + (size_t)(out - 16) * HIDDEN);
    const float4* W4 = (const float4*)(W + part * 256);
    const float4* S4 = (const float4*)(sh + part * 256);

    float a0 = 0.f, a1 = 0.f;
#pragma unroll 8
    for (int i = 0; i < 64; i += 2) {
        float4 w = W4[i],      s = S4[i];
        float4 w2 = W4[i + 1], s2 = S4[i + 1];
        a0 = fmaf(w.x, s.x, a0);   a0 = fmaf(w.y, s.y, a0);
        a0 = fmaf(w.z, s.z, a0);   a0 = fmaf(w.w, s.w, a0);
        a1 = fmaf(w2.x, s2.x, a1); a1 = fmaf(w2.y, s2.y, a1);
        a1 = fmaf(w2.z, s2.z, a1); a1 = fmaf(w2.w, s2.w, a1);
    }
    float acc = a0 + a1;
    acc += __shfl_xor_sync(0xffffffffu, acc, 1);
    acc += __shfl_xor_sync(0xffffffffu, acc, 2);
    if (part == 0) {
        if (out < 16) g_bbuf[t * HV + out] = acc;
        else          g_abuf[t * HV + (out - 16)] = acc;
    }
}

// ---------------------------------------------------------------------------
// Causal depthwise conv (KSZ=4) + silu + per-head L2 norm + gates.
// ---------------------------------------------------------------------------
__global__ __launch_bounds__(512) void conv_gate_kernel(
    const float* __restrict__ conv_w,
    const float* __restrict__ dt_bias, const float* __restrict__ A_log,
    const int* __restrict__ cu, int nseq)
{
    const int t = blockIdx.x;
    __shared__ float ybuf[CONV_DIM];
    __shared__ float ssq[16];

    int start = 0;
    for (int b = 0; b < nseq; b++) {
        int s = cu[b];
        if (t >= s) start = s;
    }

#pragma unroll
    for (int r = 0; r < 4; r++) {
        int c = threadIdx.x + 512 * r;
        float acc = 0.f;
#pragma unroll
        for (int j = 0; j < 4; j++) {
            int tt = t - 3 + j;
            if (tt >= start)
                acc = fmaf(conv_w[c * 4 + j], g_mixed[(size_t)tt * CONV_DIM + c], acc);
        }
        ybuf[c] = acc / (1.f + expf(-acc));
    }
    __syncthreads();

    {
        int w = threadIdx.x >> 5, lane = threadIdx.x & 31;
        float x0 = ybuf[w * 64 + lane];
        float x1 = ybuf[w * 64 + 32 + lane];
        float s2 = x0 * x0 + x1 * x1;
#pragma unroll
        for (int off = 16; off > 0; off >>= 1)
            s2 += __shfl_xor_sync(0xffffffffu, s2, off);
        if (lane == 0) ssq[w] = s2;
    }
    __syncthreads();

#pragma unroll
    for (int r = 0; r < 4; r++) {
        int c = threadIdx.x + 512 * r;
        float yv = ybuf[c];
        if (c < KEY_DIM) {
            int h = c >> 6;
            g_qn[(size_t)t * KEY_DIM + c] = yv * rsqrtf(ssq[h] + 1e-6f) * 0.125f;
        } else if (c < 2 * KEY_DIM) {
            int cc = c - KEY_DIM;
            int h = cc >> 6;
            g_kn[(size_t)t * KEY_DIM + cc] = yv * rsqrtf(ssq[8 + h] + 1e-6f);
        } else {
            g_vv[(size_t)t * VAL_DIM + (c - 2 * KEY_DIM)] = yv;
        }
    }

    if (threadIdx.x < HV) {
        int h = threadIdx.x;
        float bb = g_bbuf[t * HV + h];
        g_beta[t * HV + h] = 1.f / (1.f + expf(-bb));
        float aa = g_abuf[t * HV + h] + dt_bias[h];
        float sp = (aa > 20.f) ? aa : log1pf(expf(aa));
        g_gate[t * HV + h] = -expf(A_log[h]) * sp;
    }
}

// ---------------------------------------------------------------------------
// Gated delta rule recurrence, f32x2 packed math.
// grid (HV, nseq, 2); 128 threads: column c = tid>>2, row-group r = tid&3.
// ---------------------------------------------------------------------------
__global__ __launch_bounds__(128) void delta_kernel(const int* __restrict__ cu)
{
    const int h  = blockIdx.x;
    const int b  = blockIdx.y;
    const int j  = blockIdx.z * 32 + (threadIdx.x >> 2);
    const int r  = threadIdx.x & 3;
    const int i0 = r * 16;
    const int kh = h >> 1;
    const int start = cu[b], end = cu[b + 1];

    unsigned long long S2[8];
#pragma unroll
    for (int i = 0; i < 8; i++) S2[i] = 0ULL;

    unsigned long long K2[8], Q2[8], Kn[8], Qn[8];
    float vc, gc, bc, vn, gn, bn;

    auto loadT = [&](int t, unsigned long long* kk, unsigned long long* qq,
                     float& v_, float& g_, float& b_) {
        const ulonglong2* kp = (const ulonglong2*)(g_kn + (size_t)t * KEY_DIM + kh * DK + i0);
        const ulonglong2* qp = (const ulonglong2*)(g_qn + (size_t)t * KEY_DIM + kh * DK + i0);
#pragma unroll
        for (int m = 0; m < 4; m++) {
            ulonglong2 ku = kp[m], qu = qp[m];
            kk[2 * m] = ku.x; kk[2 * m + 1] = ku.y;
            qq[2 * m] = qu.x; qq[2 * m + 1] = qu.y;
        }
        v_ = g_vv[(size_t)t * VAL_DIM + h * DV + j];
        g_ = g_gate[t * HV + h];
        b_ = g_beta[t * HV + h];
    };

    if (start < end) loadT(start, K2, Q2, vc, gc, bc);

    for (int t = start; t < end; t++) {
        int tn = (t + 1 < end) ? (t + 1) : t;
        loadT(tn, Kn, Qn, vn, gn, bn);

        const float dec = expf(gc);

        unsigned long long p0 = 0ULL, p1 = 0ULL;
#pragma unroll
        for (int m = 0; m < 8; m += 2) {
            p0 = fma2(K2[m],     S2[m],     p0);
            p1 = fma2(K2[m + 1], S2[m + 1], p1);
        }
        float lo0, hi0, lo1, hi1;
        upk2(p0, lo0, hi0); upk2(p1, lo1, hi1);
        float ks = (lo0 + hi0) + (lo1 + hi1);
        ks += __shfl_xor_sync(0xffffffffu, ks, 1);
        ks += __shfl_xor_sync(0xffffffffu, ks, 2);

        const float delta = bc * (vc - dec * ks);
        const unsigned long long d2 = pk2(delta, delta);
        const unsigned long long dc2 = pk2(dec, dec);

        unsigned long long o0 = 0ULL, o1 = 0ULL;
#pragma unroll
        for (int m = 0; m < 8; m += 2) {
            unsigned long long kd0 = mul2(K2[m], d2);
            unsigned long long kd1 = mul2(K2[m + 1], d2);
            S2[m]     = fma2(dc2, S2[m],     kd0);
            S2[m + 1] = fma2(dc2, S2[m + 1], kd1);
            o0 = fma2(Q2[m],     S2[m],     o0);
            o1 = fma2(Q2[m + 1], S2[m + 1], o1);
        }
        upk2(o0, lo0, hi0); upk2(o1, lo1, hi1);
        float oo = (lo0 + hi0) + (lo1 + hi1);
        oo += __shfl_xor_sync(0xffffffffu, oo, 1);
        oo += __shfl_xor_sync(0xffffffffu, oo, 2);
        if (r == 0) g_obuf[(size_t)t * VAL_DIM + h * DV + j] = oo;

#pragma unroll
        for (int m = 0; m < 8; m++) { K2[m] = Kn[m]; Q2[m] = Qn[m]; }
        vc = vn; gc = gn; bc = bn;
    }
}

// ---------------------------------------------------------------------------
// Gated RMSNorm; output stored tf32-rounded (feeds the out-projection GEMM).
// ---------------------------------------------------------------------------
__global__ __launch_bounds__(256) void gated_norm_kernel(const float* __restrict__ nw)
{
    const int t = blockIdx.x;
    const int tid = threadIdx.x;
    const int h = tid >> 4;
    const int s = tid & 15;

    const size_t base = ((size_t)t * HV + h) * DV + s * 4;
    float4 o4 = *(const float4*)(g_obuf + base);
    float ss = o4.x * o4.x + o4.y * o4.y + o4.z * o4.z + o4.w * o4.w;
    ss += __shfl_xor_sync(0xffffffffu, ss, 8);
    ss += __shfl_xor_sync(0xffffffffu, ss, 4);
    ss += __shfl_xor_sync(0xffffffffu, ss, 2);
    ss += __shfl_xor_sync(0xffffffffu, ss, 1);
    const float rr = rsqrtf(ss * (1.f / 64.f) + 1e-6f);

    float4 z4 = *(const float4*)(g_zbuf + (size_t)t * VAL_DIM + h * DV + s * 4);
    float4 w4 = *(const float4*)(nw + s * 4);
    float4 out;
    out.x = tf32r(o4.x * rr * w4.x * (z4.x / (1.f + expf(-z4.x))));
    out.y = tf32r(o4.y * rr * w4.y * (z4.y / (1.f + expf(-z4.y))));
    out.z = tf32r(o4.z * rr * w4.z * (z4.z / (1.f + expf(-z4.z))));
    out.w = tf32r(o4.w * rr * w4.w * (z4.w / (1.f + expf(-z4.w))));
    *(float4*)(g_onrm + base) = out;
}

// ---------------------------------------------------------------------------
extern "C" void kernel_launch(void* const* d_in, const int* in_sizes, int n_in,
                              void* d_out, int out_size)
{
    const float* hidden  = (const float*)d_in[0];
    const float* W_qkv   = (const float*)d_in[1];
    const float* W_z     = (const float*)d_in[2];
    const float* W_b     = (const float*)d_in[3];
    const float* W_a     = (const float*)d_in[4];
    const float* conv_w  = (const float*)d_in[5];
    const float* dt_bias = (const float*)d_in[6];
    const float* A_log   = (const float*)d_in[7];
    const float* nw      = (const float*)d_in[8];
    const float* W_out   = (const float*)d_in[9];
    const int*   cu      = (const int*)d_in[10];

    const int total = in_sizes[0] / HIDDEN;
    const int nseq  = in_sizes[10] - 1;

    float *mixed, *zb, *on, *hidr, *wqkvr, *wzr, *woutr;
    cudaGetSymbolAddress((void**)&mixed, g_mixed);
    cudaGetSymbolAddress((void**)&zb,    g_zbuf);
    cudaGetSymbolAddress((void**)&on,    g_onrm);
    cudaGetSymbolAddress((void**)&hidr,  g_hid_r);
    cudaGetSymbolAddress((void**)&wqkvr, g_wqkv_r);
    cudaGetSymbolAddress((void**)&wzr,   g_wz_r);
    cudaGetSymbolAddress((void**)&woutr, g_wout_r);

    const int smem_bytes = SMEM_WORDS * 4;
    cudaFuncSetAttribute(gemm_tf32, cudaFuncAttributeMaxDynamicSharedMemorySize, smem_bytes);

    // 0. tf32 rounding pre-pass
    {
        int n4;
        n4 = total * HIDDEN / 4;
        round_tf32_kernel<<<(n4 + 255) / 256, 256>>>((const float4*)hidden, (float4*)hidr, n4);
        n4 = CONV_DIM * HIDDEN / 4;
        round_tf32_kernel<<<(n4 + 255) / 256, 256>>>((const float4*)W_qkv, (float4*)wqkvr, n4);
        n4 = VAL_DIM * HIDDEN / 4;
        round_tf32_kernel<<<(n4 + 255) / 256, 256>>>((const float4*)W_z, (float4*)wzr, n4);
        n4 = HIDDEN * VAL_DIM / 4;
        round_tf32_kernel<<<(n4 + 255) / 256, 256>>>((const float4*)W_out, (float4*)woutr, n4);
    }

    const int mB = (total + 127) / 128;

    // 1. big projections (pipelined tf32 tensor cores)
    gemm_tf32<<<dim3(CONV_DIM / 64, mB), 256, smem_bytes>>>(hidr, wqkvr, mixed, total, CONV_DIM, HIDDEN);
    gemm_tf32<<<dim3(VAL_DIM / 64,  mB), 256, smem_bytes>>>(hidr, wzr,   zb,    total, VAL_DIM,  HIDDEN);

    // 2. small projections (b, a fused)
    small_proj_kernel<<<total, 128>>>(hidden, W_b, W_a);

    // 3. conv + silu + norms + gates
    conv_gate_kernel<<<total, 512>>>(conv_w, dt_bias, A_log, cu, nseq);

    // 4. recurrence
    delta_kernel<<<dim3(HV, nseq, 2), 128>>>(cu);

    // 5. gated RMSNorm (tf32-rounded output)
    gated_norm_kernel<<<total, 256>>>(nw);

    // 6. output projection
    gemm_tf32<<<dim3(VAL_DIM / 64, mB), 256, smem_bytes>>>(on, woutr, (float*)d_out, total, HIDDEN, HIDDEN);
}